// round 5
// baseline (speedup 1.0000x reference)
#include <cuda_runtime.h>

// GeodesicLayer: y[n,o] = max_t sum_{b,i} h[n,b,i] * W[(b+5t)%80][i][o]
// h[n,b,i] = sum_k conn_val[n*80+b,k] * x[conn_idx[n*80+b,k], i]
//
// Constants from the reference:
#define NVERT   30000
#define BBINS   80
#define INCH    16
#define OUTCH   32
#define TBINS   16
#define PBINS   5
#define KNNZ    3

#define VT        8      // vertices per block
#define NTHREADS  256
#define HS_STRIDE 8      // h_s row stride in floats (transposed layout [1280][8])

#define W_S_FLOATS   (BBINS * INCH * OUTCH)        // 40960
#define H_S_FLOATS   (BBINS * INCH * HS_STRIDE)    // 10240
#define SMEM_BYTES   ((W_S_FLOATS + H_S_FLOATS) * 4)  // 204800

typedef unsigned long long u64;

__device__ __forceinline__ u64 dup2(float f) {
    u64 r;
    asm("mov.b64 %0, {%1, %1};" : "=l"(r) : "f"(f));
    return r;
}
__device__ __forceinline__ void fma2(u64& d, u64 a, u64 b) {
    // packed 2x fp32 FMA (Blackwell FFMA2)
    asm("fma.rn.f32x2 %0, %1, %2, %0;" : "+l"(d) : "l"(a), "l"(b));
}

__global__ __launch_bounds__(NTHREADS, 1)
void geodesic_fused_kernel(const float* __restrict__ x,
                           const int*   __restrict__ cidx,
                           const float* __restrict__ cval,
                           const float* __restrict__ wts,
                           float*       __restrict__ out)
{
    extern __shared__ float smem[];
    float* W_s = smem;                   // [80][16][32] fp32 = 160 KB
    float* h_s = smem + W_S_FLOATS;      // [1280][8] fp32 (transposed) = 40 KB

    const int tid   = threadIdx.x;
    const int vbase = blockIdx.x * VT;

    // ---- stage all weights into SMEM (coalesced float4 copy) ----
    {
        const float4* src = (const float4*)wts;
        float4*       dst = (float4*)W_s;
        #pragma unroll
        for (int j = 0; j < W_S_FLOATS / 4 / NTHREADS; ++j)   // 40 iters
            dst[tid + j * NTHREADS] = src[tid + j * NTHREADS];
    }

    // ---- gather: build h tile for 8 verts x 80 bins x 16 ch ----
    // 16 threads per conn row: lane c = channel. x row loads are 64B coalesced.
    {
        const int c  = tid & 15;
        const int rg = tid >> 4;        // 0..15 row slot
        #pragma unroll 4
        for (int r0 = 0; r0 < VT * BBINS; r0 += 16) {
            int r = r0 + rg;            // local row 0..639
            int v = r / BBINS;
            int b = r - v * BBINS;
            int grow = (vbase + v) * BBINS + b;      // < 2.4M, fits int
            const int*   ip = cidx + grow * KNNZ;
            const float* vp = cval + grow * KNNZ;
            int   i0 = ip[0], i1 = ip[1], i2 = ip[2];
            float a0 = vp[0], a1 = vp[1], a2 = vp[2];
            float acc = a0 * x[i0 * INCH + c]
                      + a1 * x[i1 * INCH + c]
                      + a2 * x[i2 * INCH + c];
            h_s[(b * INCH + c) * HS_STRIDE + v] = acc;
        }
    }
    __syncthreads();

    // ---- GEMM: thread owns (4 verts, 4 outs, one t) ----
    const int vg = tid >> 7;            // vert group: verts 4*vg .. 4*vg+3
    const int rr = tid & 127;
    const int t  = rr >> 3;             // 0..15
    const int o  = (rr & 7) << 2;       // 0,4,...,28

    u64 acc[2][4];
    #pragma unroll
    for (int a = 0; a < 2; ++a)
        #pragma unroll
        for (int c2 = 0; c2 < 4; ++c2) acc[a][c2] = 0ull;

    int wbin = PBINS * t;               // (b + 5t) % 80, maintained incrementally
    const float* hbase = h_s + vg * 4;

    #pragma unroll 1
    for (int b = 0; b < BBINS; ++b) {
        const float* wp = W_s + wbin * (INCH * OUTCH) + o;
        const float* hp = hbase + b * (INCH * HS_STRIDE);
        #pragma unroll
        for (int i = 0; i < INCH; ++i) {
            // h pair loads: 16B broadcast LDS (same addr for whole warp)
            const ulonglong2 hv = *(const ulonglong2*)(hp + i * HS_STRIDE);
            // weights: 16B per lane, 128B contiguous per t-group -> conflict-free
            const float4 w4 = *(const float4*)(wp + i * OUTCH);
            u64 w0 = dup2(w4.x), w1 = dup2(w4.y), w2 = dup2(w4.z), w3 = dup2(w4.w);
            fma2(acc[0][0], hv.x, w0);
            fma2(acc[0][1], hv.x, w1);
            fma2(acc[0][2], hv.x, w2);
            fma2(acc[0][3], hv.x, w3);
            fma2(acc[1][0], hv.y, w0);
            fma2(acc[1][1], hv.y, w1);
            fma2(acc[1][2], hv.y, w2);
            fma2(acc[1][3], hv.y, w3);
        }
        ++wbin;
        if (wbin == BBINS) wbin = 0;
    }
    __syncthreads();   // everyone done reading h_s before reuse as tmp

    // ---- stage partials tmp[t][vert][o] (reuse h_s region, 16 KB) ----
    float* tmp = h_s;
    #pragma unroll
    for (int vp2 = 0; vp2 < 2; ++vp2) {
        #pragma unroll
        for (int c2 = 0; c2 < 4; ++c2) {
            float lo, hi;
            asm("mov.b64 {%0, %1}, %2;" : "=f"(lo), "=f"(hi) : "l"(acc[vp2][c2]));
            int vlo = vg * 4 + vp2 * 2;
            tmp[(t * VT + vlo    ) * OUTCH + o + c2] = lo;
            tmp[(t * VT + vlo + 1) * OUTCH + o + c2] = hi;
        }
    }
    __syncthreads();

    // ---- max over t, one output per thread (coalesced STG) ----
    {
        int v  = tid >> 5;      // 0..7
        int oo = tid & 31;      // 0..31
        float m = tmp[(0 * VT + v) * OUTCH + oo];
        #pragma unroll
        for (int tt = 1; tt < TBINS; ++tt)
            m = fmaxf(m, tmp[(tt * VT + v) * OUTCH + oo]);
        out[(vbase + v) * OUTCH + oo] = m;
    }
}

extern "C" void kernel_launch(void* const* d_in, const int* in_sizes, int n_in,
                              void* d_out, int out_size)
{
    // metadata order: x (480000 f32), conn_idx (7.2M i32), conn_val (7.2M f32),
    // weights (40960 f32). out: 30000*32 f32.
    const float* x    = (const float*)d_in[0];
    const int*   cidx = (const int*)  d_in[1];
    const float* cval = (const float*)d_in[2];
    const float* wts  = (const float*)d_in[3];
    float* out = (float*)d_out;

    cudaFuncSetAttribute(geodesic_fused_kernel,
                         cudaFuncAttributeMaxDynamicSharedMemorySize, SMEM_BYTES);

    geodesic_fused_kernel<<<NVERT / VT, NTHREADS, SMEM_BYTES>>>(x, cidx, cval, wts, out);
}

// round 6
// speedup vs baseline: 1.0008x; 1.0008x over previous
#include <cuda_runtime.h>

// GeodesicLayer: y[n,o] = max_t sum_{b,i} h[n,b,i] * W[(b+5t)%80][i][o]
// h[n,b,i] = sum_k conn_val[n*80+b,k] * x[conn_idx[n*80+b,k], i]
//
// Constants from the reference:
#define NVERT   30000
#define BBINS   80
#define INCH    16
#define OUTCH   32
#define TBINS   16
#define PBINS   5
#define KNNZ    3

#define VT        8      // vertices per block
#define NTHREADS  256
#define HS_STRIDE 8      // h_s row stride in floats (transposed layout [1280][8])

#define W_S_FLOATS   (BBINS * INCH * OUTCH)        // 40960
#define H_S_FLOATS   (BBINS * INCH * HS_STRIDE)    // 10240
#define SMEM_BYTES   ((W_S_FLOATS + H_S_FLOATS) * 4)  // 204800

typedef unsigned long long u64;

__device__ __forceinline__ u64 dup2(float f) {
    u64 r;
    asm("mov.b64 %0, {%1, %1};" : "=l"(r) : "f"(f));
    return r;
}
__device__ __forceinline__ void fma2(u64& d, u64 a, u64 b) {
    // packed 2x fp32 FMA (Blackwell FFMA2)
    asm("fma.rn.f32x2 %0, %1, %2, %0;" : "+l"(d) : "l"(a), "l"(b));
}

__global__ __launch_bounds__(NTHREADS, 1)
void geodesic_fused_kernel(const float* __restrict__ x,
                           const int*   __restrict__ cidx,
                           const float* __restrict__ cval,
                           const float* __restrict__ wts,
                           float*       __restrict__ out)
{
    extern __shared__ float smem[];
    float* W_s = smem;                   // [80][16][32] fp32 = 160 KB
    float* h_s = smem + W_S_FLOATS;      // [1280][8] fp32 (transposed) = 40 KB

    const int tid   = threadIdx.x;
    const int vbase = blockIdx.x * VT;

    // ---- stage all weights into SMEM (coalesced float4 copy) ----
    {
        const float4* src = (const float4*)wts;
        float4*       dst = (float4*)W_s;
        #pragma unroll
        for (int j = 0; j < W_S_FLOATS / 4 / NTHREADS; ++j)   // 40 iters
            dst[tid + j * NTHREADS] = src[tid + j * NTHREADS];
    }

    // ---- gather: build h tile for 8 verts x 80 bins x 16 ch ----
    // 16 threads per conn row: lane c = channel. x row loads are 64B coalesced.
    {
        const int c  = tid & 15;
        const int rg = tid >> 4;        // 0..15 row slot
        #pragma unroll 4
        for (int r0 = 0; r0 < VT * BBINS; r0 += 16) {
            int r = r0 + rg;            // local row 0..639
            int v = r / BBINS;
            int b = r - v * BBINS;
            int grow = (vbase + v) * BBINS + b;      // < 2.4M, fits int
            const int*   ip = cidx + grow * KNNZ;
            const float* vp = cval + grow * KNNZ;
            int   i0 = ip[0], i1 = ip[1], i2 = ip[2];
            float a0 = vp[0], a1 = vp[1], a2 = vp[2];
            float acc = a0 * x[i0 * INCH + c]
                      + a1 * x[i1 * INCH + c]
                      + a2 * x[i2 * INCH + c];
            h_s[(b * INCH + c) * HS_STRIDE + v] = acc;
        }
    }
    __syncthreads();

    // ---- GEMM: thread owns (4 verts, 4 outs, one t) ----
    const int vg = tid >> 7;            // vert group: verts 4*vg .. 4*vg+3
    const int rr = tid & 127;
    const int t  = rr >> 3;             // 0..15
    const int o  = (rr & 7) << 2;       // 0,4,...,28

    u64 acc[2][4];
    #pragma unroll
    for (int a = 0; a < 2; ++a)
        #pragma unroll
        for (int c2 = 0; c2 < 4; ++c2) acc[a][c2] = 0ull;

    int wbin = PBINS * t;               // (b + 5t) % 80, maintained incrementally
    const float* hbase = h_s + vg * 4;

    #pragma unroll 1
    for (int b = 0; b < BBINS; ++b) {
        const float* wp = W_s + wbin * (INCH * OUTCH) + o;
        const float* hp = hbase + b * (INCH * HS_STRIDE);
        #pragma unroll
        for (int i = 0; i < INCH; ++i) {
            // h pair loads: 16B broadcast LDS (same addr for whole warp)
            const ulonglong2 hv = *(const ulonglong2*)(hp + i * HS_STRIDE);
            // weights: 16B per lane, 128B contiguous per t-group -> conflict-free
            const float4 w4 = *(const float4*)(wp + i * OUTCH);
            u64 w0 = dup2(w4.x), w1 = dup2(w4.y), w2 = dup2(w4.z), w3 = dup2(w4.w);
            fma2(acc[0][0], hv.x, w0);
            fma2(acc[0][1], hv.x, w1);
            fma2(acc[0][2], hv.x, w2);
            fma2(acc[0][3], hv.x, w3);
            fma2(acc[1][0], hv.y, w0);
            fma2(acc[1][1], hv.y, w1);
            fma2(acc[1][2], hv.y, w2);
            fma2(acc[1][3], hv.y, w3);
        }
        ++wbin;
        if (wbin == BBINS) wbin = 0;
    }
    __syncthreads();   // everyone done reading h_s before reuse as tmp

    // ---- stage partials tmp[t][vert][o] (reuse h_s region, 16 KB) ----
    float* tmp = h_s;
    #pragma unroll
    for (int vp2 = 0; vp2 < 2; ++vp2) {
        #pragma unroll
        for (int c2 = 0; c2 < 4; ++c2) {
            float lo, hi;
            asm("mov.b64 {%0, %1}, %2;" : "=f"(lo), "=f"(hi) : "l"(acc[vp2][c2]));
            int vlo = vg * 4 + vp2 * 2;
            tmp[(t * VT + vlo    ) * OUTCH + o + c2] = lo;
            tmp[(t * VT + vlo + 1) * OUTCH + o + c2] = hi;
        }
    }
    __syncthreads();

    // ---- max over t, one output per thread (coalesced STG) ----
    {
        int v  = tid >> 5;      // 0..7
        int oo = tid & 31;      // 0..31
        float m = tmp[(0 * VT + v) * OUTCH + oo];
        #pragma unroll
        for (int tt = 1; tt < TBINS; ++tt)
            m = fmaxf(m, tmp[(tt * VT + v) * OUTCH + oo]);
        out[(vbase + v) * OUTCH + oo] = m;
    }
}

extern "C" void kernel_launch(void* const* d_in, const int* in_sizes, int n_in,
                              void* d_out, int out_size)
{
    // metadata order: x (480000 f32), conn_idx (7.2M i32), conn_val (7.2M f32),
    // weights (40960 f32). out: 30000*32 f32.
    const float* x    = (const float*)d_in[0];
    const int*   cidx = (const int*)  d_in[1];
    const float* cval = (const float*)d_in[2];
    const float* wts  = (const float*)d_in[3];
    float* out = (float*)d_out;

    cudaFuncSetAttribute(geodesic_fused_kernel,
                         cudaFuncAttributeMaxDynamicSharedMemorySize, SMEM_BYTES);

    geodesic_fused_kernel<<<NVERT / VT, NTHREADS, SMEM_BYTES>>>(x, cidx, cval, wts, out);
}

// round 8
// speedup vs baseline: 1.6777x; 1.6763x over previous
#include <cuda_runtime.h>
#include <cuda_bf16.h>
#include <cstdint>

// GeodesicLayer via warp-level mma.sync (baseline sm_80 PTX -> HMMA on sm_103):
//   Y[n, o, t] = sum_{b,i} h[n,b,i] * W[(b+5t)%80, i, o]
//   out[n, o]  = max_t Y[n, o, t]
// h[n,b,i] = sum_k conn_val[n*80+b,k] * x[conn_idx[n*80+b,k], i]
//
// CTA: 512 threads = 16 warps; warp w accumulates t=w (M=64 verts, N=32 outs).
// B (Wflat^T, bf16 hi/lo) SMEM-resident; A (h) gathered in K-chunks of 4 bins
// (K=64), bf16 hi/lo, double-buffered. 3-term split MMA for fp32-level accuracy.

#define NVERT    30000
#define MTILE    64
#define NCTAS    ((NVERT + MTILE - 1) / MTILE)   // 469
#define NTHREADS 512

// ---- SMEM layout (bytes) ----
// Bt[n][k]: n=0..31 rows, k=0..1279, row stride padded to 1288 elements (2576 B)
#define BT_STRIDE_EL 1288
#define BT_BYTES     (32 * BT_STRIDE_EL * 2)      // 82432
#define OFF_BHI      0
#define OFF_BLO      BT_BYTES                     // 82432
#define OFF_A        (2 * BT_BYTES)               // 164864 (16B aligned)
// A chunk: [64 m][64 k] bf16, row stride padded to 72 el (144 B): 9216 B
#define A_ROW_B      144
#define A_HI_BYTES   (64 * A_ROW_B)               // 9216
#define A_BUF_BYTES  (2 * A_HI_BYTES)             // hi+lo = 18432
#define SMEM_TOTAL   (OFF_A + 2 * A_BUF_BYTES)    // 201728

// epilogue slab: [16 t][64 v][32 o] fp32, v-stride padded to 136 B
#define SLAB_T_B  8704
#define SLAB_V_B  136

typedef unsigned int u32;

__device__ __forceinline__ u32 s2u(const void* p) {
    u32 a;
    asm("{ .reg .u64 t; cvta.to.shared.u64 t, %1; cvt.u32.u64 %0, t; }"
        : "=r"(a) : "l"(p));
    return a;
}

__device__ __forceinline__ void ldsm4(u32& r0, u32& r1, u32& r2, u32& r3, u32 addr) {
    asm volatile("ldmatrix.sync.aligned.m8n8.x4.shared.b16 {%0,%1,%2,%3}, [%4];"
        : "=r"(r0), "=r"(r1), "=r"(r2), "=r"(r3) : "r"(addr));
}

__device__ __forceinline__ void mma_bf16(float* d, const u32* a, u32 b0, u32 b1) {
    asm volatile(
        "mma.sync.aligned.m16n8k16.row.col.f32.bf16.bf16.f32 "
        "{%0,%1,%2,%3}, {%4,%5,%6,%7}, {%8,%9}, {%0,%1,%2,%3};"
        : "+f"(d[0]), "+f"(d[1]), "+f"(d[2]), "+f"(d[3])
        : "r"(a[0]), "r"(a[1]), "r"(a[2]), "r"(a[3]), "r"(b0), "r"(b1));
}

__global__ __launch_bounds__(NTHREADS, 1)
void geo_mma_kernel(const float* __restrict__ x,
                    const int*   __restrict__ cidx,
                    const float* __restrict__ cval,
                    const float* __restrict__ wts,
                    float*       __restrict__ out)
{
    extern __shared__ char smem[];
    const u32 sb    = s2u(smem);
    const int tid   = threadIdx.x;
    const int warp  = tid >> 5;          // == t value this warp accumulates
    const int lane  = tid & 31;
    const int vbase = blockIdx.x * MTILE;
    const int vlim  = min(MTILE, NVERT - vbase);

    // ---- stage Bt[n][k] = wts[k*32+n] as bf16 hi/lo ----
    for (int idx = tid; idx < 40960; idx += NTHREADS) {
        float w = wts[idx];
        int k = idx >> 5, n = idx & 31;
        __nv_bfloat16 hi = __float2bfloat16(w);
        __nv_bfloat16 lo = __float2bfloat16(w - __bfloat162float(hi));
        u32 off = (u32)(n * BT_STRIDE_EL + k) * 2;
        *(__nv_bfloat16*)(smem + OFF_BHI + off) = hi;
        *(__nv_bfloat16*)(smem + OFF_BLO + off) = lo;
    }
    __syncthreads();

    // accumulators: acc[mt][nt][4]  (warp tile M=64, N=32 for t=warp)
    float acc[4][4][4];
    #pragma unroll
    for (int m = 0; m < 4; ++m)
        #pragma unroll
        for (int n = 0; n < 4; ++n)
            #pragma unroll
            for (int q = 0; q < 4; ++q) acc[m][n][q] = 0.f;

    // per-lane ldmatrix address components
    // A tile [16m x 16k]: m0 lanes0-7 rows0-7 k0-7; m1 lanes8-15 rows8-15 k0-7;
    //                     m2 lanes16-23 rows0-7 k8-15; m3 lanes24-31 rows8-15 k8-15
    const u32 a_lane = (u32)(((lane & 7) + ((lane >> 3) & 1) * 8) * A_ROW_B
                             + ((lane >> 4) & 1) * 16);
    // B tile [16n x 16k] of Bt: m0 lanes0-7 n0-7 k0-7; m1 lanes8-15 n0-7 k8-15;
    //                           m2 lanes16-23 n8-15 k0-7; m3 lanes24-31 n8-15 k8-15
    const u32 b_row  = (u32)((lane & 7) + ((lane >> 4) & 1) * 8);
    const u32 b_lane = b_row * (BT_STRIDE_EL * 2) + (u32)(((lane >> 3) & 1) * 16);

    const int gc  = tid & 15;   // gather channel lane
    const int gsl = tid >> 4;   // gather row slot 0..31

    for (int c = 0; c < 20; ++c) {
        const int buf = c & 1;
        char* ahi = smem + OFF_A + buf * A_BUF_BYTES;
        char* alo = ahi + A_HI_BYTES;

        // ---- gather phase: 4 bins x 64 verts x 16 ch = 4096 h values ----
        #pragma unroll
        for (int it = 0; it < 8; ++it) {
            int r  = it * 32 + gsl;     // 0..255 = v*4 + bl
            int v  = r >> 2;
            int bl = r & 3;
            float h = 0.f;
            if (v < vlim) {
                int grow = (vbase + v) * 80 + (c * 4 + bl);
                const int*   ip = cidx + grow * 3;
                const float* vp = cval + grow * 3;
                h = vp[0] * __ldg(x + ip[0] * 16 + gc)
                  + vp[1] * __ldg(x + ip[1] * 16 + gc)
                  + vp[2] * __ldg(x + ip[2] * 16 + gc);
            }
            __nv_bfloat16 hi = __float2bfloat16(h);
            __nv_bfloat16 lo = __float2bfloat16(h - __bfloat162float(hi));
            u32 off = (u32)(v * A_ROW_B + (bl * 16 + gc) * 2);
            *(__nv_bfloat16*)(ahi + off) = hi;
            *(__nv_bfloat16*)(alo + off) = lo;
        }
        __syncthreads();

        // ---- MMA phase: this warp's t, 4 k-tiles (bins) ----
        const u32 abase = sb + OFF_A + buf * A_BUF_BYTES;
        const u32 bhibase = sb + OFF_BHI;
        const u32 blobase = sb + OFF_BLO;
        int wbin = (4 * c + 5 * warp) % 80;

        #pragma unroll
        for (int j = 0; j < 4; ++j) {
            const u32 boff = b_lane + (u32)wbin * 32;
            u32 bh[2][4], bl2[2][4];
            ldsm4(bh[0][0], bh[0][1], bh[0][2], bh[0][3], bhibase + boff);
            ldsm4(bh[1][0], bh[1][1], bh[1][2], bh[1][3],
                  bhibase + boff + 16 * BT_STRIDE_EL * 2);
            ldsm4(bl2[0][0], bl2[0][1], bl2[0][2], bl2[0][3], blobase + boff);
            ldsm4(bl2[1][0], bl2[1][1], bl2[1][2], bl2[1][3],
                  blobase + boff + 16 * BT_STRIDE_EL * 2);

            #pragma unroll
            for (int mt = 0; mt < 4; ++mt) {
                const u32 aaddr = abase + (u32)(mt * 16 * A_ROW_B + j * 32) + a_lane;
                u32 ah[4], al[4];
                ldsm4(ah[0], ah[1], ah[2], ah[3], aaddr);
                ldsm4(al[0], al[1], al[2], al[3], aaddr + A_HI_BYTES);
                #pragma unroll
                for (int nt = 0; nt < 4; ++nt) {
                    u32 b0h = bh[nt >> 1][(nt & 1) * 2];
                    u32 b1h = bh[nt >> 1][(nt & 1) * 2 + 1];
                    u32 b0l = bl2[nt >> 1][(nt & 1) * 2];
                    u32 b1l = bl2[nt >> 1][(nt & 1) * 2 + 1];
                    mma_bf16(acc[mt][nt], ah, b0h, b1h);  // hi*hi
                    mma_bf16(acc[mt][nt], ah, b0l, b1l);  // hi*lo
                    mma_bf16(acc[mt][nt], al, b0h, b1h);  // lo*hi
                }
            }
            ++wbin; if (wbin == 80) wbin = 0;
        }
        __syncthreads();   // before gather overwrites buf (2 chunks later) / B reuse
    }

    // ---- epilogue: write acc slabs [t][v][o] to SMEM, max over t, store ----
    {
        char* slab = smem + warp * SLAB_T_B;
        #pragma unroll
        for (int mt = 0; mt < 4; ++mt) {
            #pragma unroll
            for (int nt = 0; nt < 4; ++nt) {
                int v = mt * 16 + (lane >> 2);
                u32 ob = (u32)(nt * 32 + (lane & 3) * 8);
                *(float2*)(slab + v * SLAB_V_B + ob) =
                    make_float2(acc[mt][nt][0], acc[mt][nt][1]);
                *(float2*)(slab + (v + 8) * SLAB_V_B + ob) =
                    make_float2(acc[mt][nt][2], acc[mt][nt][3]);
            }
        }
    }
    __syncthreads();

    #pragma unroll
    for (int idx = tid; idx < MTILE * 32; idx += NTHREADS) {
        int v = idx >> 5, o = idx & 31;
        const char* p = smem + v * SLAB_V_B + o * 4;
        float m = *(const float*)p;
        #pragma unroll
        for (int t = 1; t < 16; ++t)
            m = fmaxf(m, *(const float*)(p + t * SLAB_T_B));
        if (v < vlim)
            out[(size_t)(vbase + v) * 32 + o] = m;
    }
}

extern "C" void kernel_launch(void* const* d_in, const int* in_sizes, int n_in,
                              void* d_out, int out_size)
{
    const float* x    = (const float*)d_in[0];
    const int*   cidx = (const int*)  d_in[1];
    const float* cval = (const float*)d_in[2];
    const float* wts  = (const float*)d_in[3];
    float* out = (float*)d_out;

    cudaFuncSetAttribute(geo_mma_kernel,
                         cudaFuncAttributeMaxDynamicSharedMemorySize, SMEM_TOTAL);

    geo_mma_kernel<<<NCTAS, NTHREADS, SMEM_TOTAL>>>(x, cidx, cval, wts, out);
}

// round 9
// speedup vs baseline: 2.0281x; 1.2089x over previous
#include <cuda_runtime.h>
#include <cuda_bf16.h>
#include <cstdint>

// GeodesicLayer, two-kernel split:
//  K1: h[v,b,i] = sum_k conn_val*x[conn_idx] -> gmem as bf16 hi/lo ([30016][1280])
//  K2: Y[n,o,t] = sum_{b,i} h[n,b,i]*W[(b+5t)%80,i,o] via mma.sync bf16 3-term
//      split, A streamed with cp.async (3 stages), out = max_t Y.

#define NVERT 30000
#define NVPAD 30016
#define KTOT  1280

__device__ __nv_bfloat16 g_hhi[(size_t)NVPAD * KTOT];
__device__ __nv_bfloat16 g_hlo[(size_t)NVPAD * KTOT];

typedef unsigned int u32;

// ====================== kernel 1: gather ======================
__global__ __launch_bounds__(256)
void geo_gather_kernel(const float* __restrict__ x,
                       const int*   __restrict__ cidx,
                       const float* __restrict__ cval)
{
    const int tid = threadIdx.x;
    const int row = blockIdx.x * 16 + (tid >> 4);   // global conn row = v*80+b
    const int c   = tid & 15;
    const int*   ip = cidx + (size_t)row * 3;
    const float* vp = cval + (size_t)row * 3;
    float h = vp[0] * __ldg(x + ip[0] * 16 + c)
            + vp[1] * __ldg(x + ip[1] * 16 + c)
            + vp[2] * __ldg(x + ip[2] * 16 + c);
    __nv_bfloat16 hi = __float2bfloat16(h);
    __nv_bfloat16 lo = __float2bfloat16(h - __bfloat162float(hi));
    size_t o = (size_t)row * 16 + c;                // == v*1280 + b*16 + c
    g_hhi[o] = hi;
    g_hlo[o] = lo;
}

// ====================== kernel 2: GEMM + max ======================
#define MTILE    64
#define NCTAS    ((NVPAD) / MTILE)                 // 469
#define NTHREADS 512

#define BT_STRIDE_EL 1288
#define BT_BYTES     (32 * BT_STRIDE_EL * 2)       // 82432
#define OFF_BHI      0
#define OFF_BLO      BT_BYTES
#define OFF_A        (2 * BT_BYTES)                // 164864
#define A_ROW_B      144
#define A_HI_BYTES   (64 * A_ROW_B)                // 9216
#define A_STAGE      (2 * A_HI_BYTES)              // 18432
#define NSTAGES      3
#define SMEM_TOTAL   (OFF_A + NSTAGES * A_STAGE)   // 220160

#define SLAB_T_B  8704
#define SLAB_V_B  136

__device__ __forceinline__ u32 s2u(const void* p) {
    u32 a;
    asm("{ .reg .u64 t; cvta.to.shared.u64 t, %1; cvt.u32.u64 %0, t; }"
        : "=r"(a) : "l"(p));
    return a;
}
__device__ __forceinline__ void ldsm4(u32& r0, u32& r1, u32& r2, u32& r3, u32 addr) {
    asm volatile("ldmatrix.sync.aligned.m8n8.x4.shared.b16 {%0,%1,%2,%3}, [%4];"
        : "=r"(r0), "=r"(r1), "=r"(r2), "=r"(r3) : "r"(addr));
}
__device__ __forceinline__ void mma_bf16(float* d, const u32* a, u32 b0, u32 b1) {
    asm volatile(
        "mma.sync.aligned.m16n8k16.row.col.f32.bf16.bf16.f32 "
        "{%0,%1,%2,%3}, {%4,%5,%6,%7}, {%8,%9}, {%0,%1,%2,%3};"
        : "+f"(d[0]), "+f"(d[1]), "+f"(d[2]), "+f"(d[3])
        : "r"(a[0]), "r"(a[1]), "r"(a[2]), "r"(a[3]), "r"(b0), "r"(b1));
}
__device__ __forceinline__ void cp16(u32 dst, const void* src) {
    asm volatile("cp.async.cg.shared.global [%0], [%1], 16;"
                 :: "r"(dst), "l"(src) : "memory");
}

// copy A chunk c (k = c*64..c*64+63, bf16) into stage s; 2 cp.async per thread
__device__ __forceinline__ void issue_copy(int c, int s, u32 sb, int vbase, int tid)
{
    const int arr = tid >> 8;            // 0 = hi, 1 = lo
    const int row = (tid >> 2) & 63;
    const int q0  = tid & 3;
    const __nv_bfloat16* src = (arr ? g_hlo : g_hhi)
        + (size_t)(vbase + row) * KTOT + c * 64;
    const u32 dst = sb + OFF_A + s * A_STAGE + arr * A_HI_BYTES + row * A_ROW_B;
    cp16(dst + q0 * 16,       src + q0 * 8);
    cp16(dst + (q0 + 4) * 16, src + (q0 + 4) * 8);
}

__global__ __launch_bounds__(NTHREADS, 1)
void geo_mma_kernel(const float* __restrict__ wts, float* __restrict__ out)
{
    extern __shared__ char smem[];
    const u32 sb    = s2u(smem);
    const int tid   = threadIdx.x;
    const int warp  = tid >> 5;          // == t value
    const int lane  = tid & 31;
    const int vbase = blockIdx.x * MTILE;
    const int vlim  = min(MTILE, NVERT - vbase);

    // prologue: start A pipeline (overlaps with B staging below)
    issue_copy(0, 0, sb, vbase, tid);
    asm volatile("cp.async.commit_group;" ::: "memory");
    issue_copy(1, 1, sb, vbase, tid);
    asm volatile("cp.async.commit_group;" ::: "memory");
    issue_copy(2, 2, sb, vbase, tid);
    asm volatile("cp.async.commit_group;" ::: "memory");

    // stage Bt[n][k] = wts[k*32+n] as bf16 hi/lo
    for (int idx = tid; idx < 40960; idx += NTHREADS) {
        float w = wts[idx];
        int k = idx >> 5, n = idx & 31;
        __nv_bfloat16 hi = __float2bfloat16(w);
        __nv_bfloat16 lo = __float2bfloat16(w - __bfloat162float(hi));
        u32 off = (u32)(n * BT_STRIDE_EL + k) * 2;
        *(__nv_bfloat16*)(smem + OFF_BHI + off) = hi;
        *(__nv_bfloat16*)(smem + OFF_BLO + off) = lo;
    }

    float acc[4][4][4];
    #pragma unroll
    for (int m = 0; m < 4; ++m)
        #pragma unroll
        for (int n = 0; n < 4; ++n)
            #pragma unroll
            for (int q = 0; q < 4; ++q) acc[m][n][q] = 0.f;

    // ldmatrix lane addressing (validated in round 8)
    const u32 a_lane = (u32)(((lane & 7) + ((lane >> 3) & 1) * 8) * A_ROW_B
                             + ((lane >> 4) & 1) * 16);
    const u32 b_row  = (u32)((lane & 7) + ((lane >> 4) & 1) * 8);
    const u32 b_lane = b_row * (BT_STRIDE_EL * 2) + (u32)(((lane >> 3) & 1) * 16);
    const u32 bhibase = sb + OFF_BHI;
    const u32 blobase = sb + OFF_BLO;

    for (int c = 0; c < 20; ++c) {
        const int s = c % NSTAGES;
        asm volatile("cp.async.wait_group 2;" ::: "memory");
        __syncthreads();                 // stage s data visible to all warps

        const u32 abase = sb + OFF_A + s * A_STAGE;
        int wbin = (4 * c + 5 * warp) % 80;

        #pragma unroll
        for (int j = 0; j < 4; ++j) {
            const u32 boff = b_lane + (u32)wbin * 32;
            u32 bh[2][4], bl[2][4];
            ldsm4(bh[0][0], bh[0][1], bh[0][2], bh[0][3], bhibase + boff);
            ldsm4(bh[1][0], bh[1][1], bh[1][2], bh[1][3],
                  bhibase + boff + 16 * BT_STRIDE_EL * 2);
            ldsm4(bl[0][0], bl[0][1], bl[0][2], bl[0][3], blobase + boff);
            ldsm4(bl[1][0], bl[1][1], bl[1][2], bl[1][3],
                  blobase + boff + 16 * BT_STRIDE_EL * 2);

            #pragma unroll
            for (int mt = 0; mt < 4; ++mt) {
                const u32 aaddr = abase + (u32)(mt * 16 * A_ROW_B + j * 32) + a_lane;
                u32 ah[4], al[4];
                ldsm4(ah[0], ah[1], ah[2], ah[3], aaddr);
                ldsm4(al[0], al[1], al[2], al[3], aaddr + A_HI_BYTES);
                // term-major: RAW distance 4 instead of 1
                #pragma unroll
                for (int nt = 0; nt < 4; ++nt)
                    mma_bf16(acc[mt][nt], ah,
                             bh[nt >> 1][(nt & 1) * 2], bh[nt >> 1][(nt & 1) * 2 + 1]);
                #pragma unroll
                for (int nt = 0; nt < 4; ++nt)
                    mma_bf16(acc[mt][nt], ah,
                             bl[nt >> 1][(nt & 1) * 2], bl[nt >> 1][(nt & 1) * 2 + 1]);
                #pragma unroll
                for (int nt = 0; nt < 4; ++nt)
                    mma_bf16(acc[mt][nt], al,
                             bh[nt >> 1][(nt & 1) * 2], bh[nt >> 1][(nt & 1) * 2 + 1]);
            }
            ++wbin; if (wbin == 80) wbin = 0;
        }
        __syncthreads();                 // all warps done with stage s
        if (c + NSTAGES < 20)
            issue_copy(c + NSTAGES, s, sb, vbase, tid);
        asm volatile("cp.async.commit_group;" ::: "memory");  // keep group count aligned
    }

    // epilogue: slab [t][v][o] in smem, max over t, store
    __syncthreads();
    {
        char* slab = smem + warp * SLAB_T_B;
        #pragma unroll
        for (int mt = 0; mt < 4; ++mt) {
            #pragma unroll
            for (int nt = 0; nt < 4; ++nt) {
                int v = mt * 16 + (lane >> 2);
                u32 ob = (u32)(nt * 32 + (lane & 3) * 8);
                *(float2*)(slab + v * SLAB_V_B + ob) =
                    make_float2(acc[mt][nt][0], acc[mt][nt][1]);
                *(float2*)(slab + (v + 8) * SLAB_V_B + ob) =
                    make_float2(acc[mt][nt][2], acc[mt][nt][3]);
            }
        }
    }
    __syncthreads();

    for (int idx = tid; idx < MTILE * 32; idx += NTHREADS) {
        int v = idx >> 5, o = idx & 31;
        const char* p = smem + v * SLAB_V_B + o * 4;
        float m = *(const float*)p;
        #pragma unroll
        for (int t = 1; t < 16; ++t)
            m = fmaxf(m, *(const float*)(p + t * SLAB_T_B));
        if (v < vlim)
            out[(size_t)(vbase + v) * 32 + o] = m;
    }
}

extern "C" void kernel_launch(void* const* d_in, const int* in_sizes, int n_in,
                              void* d_out, int out_size)
{
    const float* x    = (const float*)d_in[0];
    const int*   cidx = (const int*)  d_in[1];
    const float* cval = (const float*)d_in[2];
    const float* wts  = (const float*)d_in[3];
    float* out = (float*)d_out;

    geo_gather_kernel<<<(NVERT * 80) / 16, 256>>>(x, cidx, cval);

    cudaFuncSetAttribute(geo_mma_kernel,
                         cudaFuncAttributeMaxDynamicSharedMemorySize, SMEM_TOTAL);
    geo_mma_kernel<<<NCTAS, NTHREADS, SMEM_TOTAL>>>(wts, out);
}

// round 10
// speedup vs baseline: 2.1577x; 1.0639x over previous
#include <cuda_runtime.h>
#include <cuda_bf16.h>
#include <cstdint>

// GeodesicLayer, three-kernel split:
//  K0: W -> bf16 hi/lo in padded Bt[n][k] layout (gmem, copied to smem by K2)
//  K1: h[v,b,i] = sum_k conn_val*x[conn_idx] -> gmem bf16 hi/lo [30016][1280]
//      (conn staged in smem via cp.async; 2 rows/thread, float4 x loads)
//  K2: Y[n,o,t] = sum h*W[(b+5t)%80] via mma.sync bf16 3-term split,
//      A streamed with cp.async (3 stages, single-sync pipeline), out = max_t.

#define NVERT 30000
#define NVPAD 30016
#define KTOT  1280
#define NROWS (NVERT * 80)                     // 2,400,000

#define BT_STRIDE_EL 1288

__device__ __nv_bfloat16 g_hhi[(size_t)NVPAD * KTOT];
__device__ __nv_bfloat16 g_hlo[(size_t)NVPAD * KTOT];
__device__ __nv_bfloat16 g_bt[2 * 32 * BT_STRIDE_EL];   // hi then lo

typedef unsigned int u32;

__device__ __forceinline__ u32 s2u(const void* p) {
    u32 a;
    asm("{ .reg .u64 t; cvta.to.shared.u64 t, %1; cvt.u32.u64 %0, t; }"
        : "=r"(a) : "l"(p));
    return a;
}
// pack two f32 -> bf16x2 (lo lane = flo)
__device__ __forceinline__ u32 packbf(float fhi, float flo) {
    u32 r;
    asm("cvt.rn.bf16x2.f32 %0, %1, %2;" : "=r"(r) : "f"(fhi), "f"(flo));
    return r;
}

// ====================== kernel 0: prep B ======================
__global__ __launch_bounds__(512)
void geo_prep_b(const float* __restrict__ wts)
{
    const int i0 = blockIdx.x * 1024 + threadIdx.x;
    #pragma unroll
    for (int rep = 0; rep < 2; ++rep) {
        int idx = i0 + rep * 512;             // 0..40959
        float w = wts[idx];
        int k = idx >> 5, n = idx & 31;
        __nv_bfloat16 hi = __float2bfloat16(w);
        __nv_bfloat16 lo = __float2bfloat16(w - __bfloat162float(hi));
        g_bt[n * BT_STRIDE_EL + k] = hi;
        g_bt[32 * BT_STRIDE_EL + n * BT_STRIDE_EL + k] = lo;
    }
}

// ====================== kernel 1: gather ======================
#define RPB 512
#define K1T 256

__global__ __launch_bounds__(K1T)
void geo_gather_kernel(const float* __restrict__ x,
                       const int*   __restrict__ cidx,
                       const float* __restrict__ cval)
{
    __shared__ int   s_idx[RPB * 3];          // 6 KB
    __shared__ float s_val[RPB * 3];          // 6 KB
    const int tid  = threadIdx.x;
    const long base = (long)blockIdx.x * RPB;

    // stage conn slice: 2 x 6144 B, 16B cp.async chunks, zero-fill OOB
    {
        const int vrows = (int)min((long)RPB, (long)NROWS - base);
        const int vb = vrows * 12;            // multiple of 16 here
        const char* si = (const char*)(cidx + base * 3);
        const char* sv = (const char*)(cval + base * 3);
        const u32 di = s2u(s_idx), dv = s2u(s_val);
        for (int q = tid; q < 384; q += K1T) {
            int sz = (q * 16 + 16 <= vb) ? 16 : 0;
            asm volatile("cp.async.cg.shared.global [%0], [%1], 16, %2;"
                         :: "r"(di + q * 16), "l"(si + q * 16), "r"(sz) : "memory");
            asm volatile("cp.async.cg.shared.global [%0], [%1], 16, %2;"
                         :: "r"(dv + q * 16), "l"(sv + q * 16), "r"(sz) : "memory");
        }
        asm volatile("cp.async.commit_group;" ::: "memory");
        asm volatile("cp.async.wait_group 0;" ::: "memory");
        __syncthreads();
    }

    const float4* xp = (const float4*)x;
    uint4* dh = (uint4*)g_hhi;
    uint4* dl = (uint4*)g_hlo;

    #pragma unroll
    for (int rr = 0; rr < 2; ++rr) {
        const long grow = base + 2 * tid + rr;
        if (grow < NROWS) {
            const int lr = 2 * tid + rr;
            const int i0 = s_idx[lr * 3], i1 = s_idx[lr * 3 + 1], i2 = s_idx[lr * 3 + 2];
            const float v0 = s_val[lr * 3], v1 = s_val[lr * 3 + 1], v2 = s_val[lr * 3 + 2];
            float4 h4[4];
            #pragma unroll
            for (int j = 0; j < 4; ++j) {
                float4 a = xp[i0 * 4 + j];
                float4 b = xp[i1 * 4 + j];
                float4 c = xp[i2 * 4 + j];
                h4[j].x = v0 * a.x + v1 * b.x + v2 * c.x;
                h4[j].y = v0 * a.y + v1 * b.y + v2 * c.y;
                h4[j].z = v0 * a.z + v1 * b.z + v2 * c.z;
                h4[j].w = v0 * a.w + v1 * b.w + v2 * c.w;
            }
            const float* f = (const float*)h4;
            u32 hi[8], lo[8];
            #pragma unroll
            for (int p = 0; p < 8; ++p) {
                float f0 = f[2 * p], f1 = f[2 * p + 1];
                u32 hp = packbf(f1, f0);
                float g0 = __uint_as_float(hp << 16);
                float g1 = __uint_as_float(hp & 0xffff0000u);
                hi[p] = hp;
                lo[p] = packbf(f1 - g1, f0 - g0);
            }
            dh[grow * 2]     = make_uint4(hi[0], hi[1], hi[2], hi[3]);
            dh[grow * 2 + 1] = make_uint4(hi[4], hi[5], hi[6], hi[7]);
            dl[grow * 2]     = make_uint4(lo[0], lo[1], lo[2], lo[3]);
            dl[grow * 2 + 1] = make_uint4(lo[4], lo[5], lo[6], lo[7]);
        }
    }
}

// ====================== kernel 2: GEMM + max ======================
#define MTILE    64
#define NCTAS    (NVPAD / MTILE)               // 469
#define NTHREADS 512

#define BT_BYTES     (32 * BT_STRIDE_EL * 2)   // 82432
#define OFF_BHI      0
#define OFF_BLO      BT_BYTES
#define OFF_A        (2 * BT_BYTES)            // 164864
#define A_ROW_B      144
#define A_HI_BYTES   (64 * A_ROW_B)            // 9216
#define A_STAGE      (2 * A_HI_BYTES)          // 18432
#define NSTAGES      3
#define SMEM_TOTAL   (OFF_A + NSTAGES * A_STAGE)  // 220160

#define SLAB_T_B  8704
#define SLAB_V_B  136

__device__ __forceinline__ void ldsm4(u32& r0, u32& r1, u32& r2, u32& r3, u32 addr) {
    asm volatile("ldmatrix.sync.aligned.m8n8.x4.shared.b16 {%0,%1,%2,%3}, [%4];"
        : "=r"(r0), "=r"(r1), "=r"(r2), "=r"(r3) : "r"(addr));
}
__device__ __forceinline__ void mma_bf16(float* d, const u32* a, u32 b0, u32 b1) {
    asm volatile(
        "mma.sync.aligned.m16n8k16.row.col.f32.bf16.bf16.f32 "
        "{%0,%1,%2,%3}, {%4,%5,%6,%7}, {%8,%9}, {%0,%1,%2,%3};"
        : "+f"(d[0]), "+f"(d[1]), "+f"(d[2]), "+f"(d[3])
        : "r"(a[0]), "r"(a[1]), "r"(a[2]), "r"(a[3]), "r"(b0), "r"(b1));
}
__device__ __forceinline__ void cp16(u32 dst, const void* src) {
    asm volatile("cp.async.cg.shared.global [%0], [%1], 16;"
                 :: "r"(dst), "l"(src) : "memory");
}

__device__ __forceinline__ void issue_copy(int c, int s, u32 sb, int vbase, int tid)
{
    const int arr = tid >> 8;              // 0 = hi, 1 = lo
    const int row = (tid >> 2) & 63;
    const int q0  = tid & 3;
    const __nv_bfloat16* src = (arr ? g_hlo : g_hhi)
        + (size_t)(vbase + row) * KTOT + c * 64;
    const u32 dst = sb + OFF_A + s * A_STAGE + arr * A_HI_BYTES + row * A_ROW_B;
    cp16(dst + q0 * 16,       src + q0 * 8);
    cp16(dst + (q0 + 4) * 16, src + (q0 + 4) * 8);
}

__global__ __launch_bounds__(NTHREADS, 1)
void geo_mma_kernel(float* __restrict__ out)
{
    extern __shared__ char smem[];
    const u32 sb    = s2u(smem);
    const int tid   = threadIdx.x;
    const int warp  = tid >> 5;            // == t value
    const int lane  = tid & 31;
    const int vbase = blockIdx.x * MTILE;
    const int vlim  = min(MTILE, NVERT - vbase);

    // group 0: B copy (linear, padded layout matches smem exactly)
    {
        const char* src = (const char*)g_bt;
        for (int q = tid; q < BT_BYTES * 2 / 16; q += NTHREADS)   // 10304 chunks
            cp16(sb + q * 16, src + q * 16);
        asm volatile("cp.async.commit_group;" ::: "memory");
    }
    // groups 1,2: A chunks 0,1
    issue_copy(0, 0, sb, vbase, tid);
    asm volatile("cp.async.commit_group;" ::: "memory");
    issue_copy(1, 1, sb, vbase, tid);
    asm volatile("cp.async.commit_group;" ::: "memory");

    float acc[4][4][4];
    #pragma unroll
    for (int m = 0; m < 4; ++m)
        #pragma unroll
        for (int n = 0; n < 4; ++n)
            #pragma unroll
            for (int q = 0; q < 4; ++q) acc[m][n][q] = 0.f;

    // ldmatrix lane addressing (validated round 8)
    const u32 a_lane = (u32)(((lane & 7) + ((lane >> 3) & 1) * 8) * A_ROW_B
                             + ((lane >> 4) & 1) * 16);
    const u32 b_row  = (u32)((lane & 7) + ((lane >> 4) & 1) * 8);
    const u32 b_lane = b_row * (BT_STRIDE_EL * 2) + (u32)(((lane >> 3) & 1) * 16);
    const u32 bhibase = sb + OFF_BHI;
    const u32 blobase = sb + OFF_BLO;

    for (int c = 0; c < 20; ++c) {
        const int s = c % NSTAGES;
        // retire groups up to and including chunk c's (B retired at c=0)
        asm volatile("cp.async.wait_group 1;" ::: "memory");
        __syncthreads();   // chunk c visible everywhere; all finished chunk c-1

        // stage (c+2)%3 == (c-1)%3 is now free: refill it
        if (c + 2 < 20)
            issue_copy(c + 2, (c + 2) % NSTAGES, sb, vbase, tid);
        asm volatile("cp.async.commit_group;" ::: "memory");

        const u32 abase = sb + OFF_A + s * A_STAGE;
        int wbin = (4 * c + 5 * warp) % 80;

        #pragma unroll
        for (int j = 0; j < 4; ++j) {
            const u32 boff = b_lane + (u32)wbin * 32;
            u32 bh[2][4], bl[2][4];
            ldsm4(bh[0][0], bh[0][1], bh[0][2], bh[0][3], bhibase + boff);
            ldsm4(bh[1][0], bh[1][1], bh[1][2], bh[1][3],
                  bhibase + boff + 16 * BT_STRIDE_EL * 2);
            ldsm4(bl[0][0], bl[0][1], bl[0][2], bl[0][3], blobase + boff);
            ldsm4(bl[1][0], bl[1][1], bl[1][2], bl[1][3],
                  blobase + boff + 16 * BT_STRIDE_EL * 2);

            #pragma unroll
            for (int mt = 0; mt < 4; ++mt) {
                const u32 aaddr = abase + (u32)(mt * 16 * A_ROW_B + j * 32) + a_lane;
                u32 ah[4], al[4];
                ldsm4(ah[0], ah[1], ah[2], ah[3], aaddr);
                ldsm4(al[0], al[1], al[2], al[3], aaddr + A_HI_BYTES);
                #pragma unroll
                for (int nt = 0; nt < 4; ++nt)
                    mma_bf16(acc[mt][nt], ah,
                             bh[nt >> 1][(nt & 1) * 2], bh[nt >> 1][(nt & 1) * 2 + 1]);
                #pragma unroll
                for (int nt = 0; nt < 4; ++nt)
                    mma_bf16(acc[mt][nt], ah,
                             bl[nt >> 1][(nt & 1) * 2], bl[nt >> 1][(nt & 1) * 2 + 1]);
                #pragma unroll
                for (int nt = 0; nt < 4; ++nt)
                    mma_bf16(acc[mt][nt], al,
                             bh[nt >> 1][(nt & 1) * 2], bh[nt >> 1][(nt & 1) * 2 + 1]);
            }
            ++wbin; if (wbin == 80) wbin = 0;
        }
    }

    // epilogue: slab [t][v][o] (overwrites B region), max over t, store
    __syncthreads();
    {
        char* slab = smem + warp * SLAB_T_B;
        #pragma unroll
        for (int mt = 0; mt < 4; ++mt) {
            #pragma unroll
            for (int nt = 0; nt < 4; ++nt) {
                int v = mt * 16 + (lane >> 2);
                u32 ob = (u32)(nt * 32 + (lane & 3) * 8);
                *(float2*)(slab + v * SLAB_V_B + ob) =
                    make_float2(acc[mt][nt][0], acc[mt][nt][1]);
                *(float2*)(slab + (v + 8) * SLAB_V_B + ob) =
                    make_float2(acc[mt][nt][2], acc[mt][nt][3]);
            }
        }
    }
    __syncthreads();

    for (int idx = tid; idx < MTILE * 32; idx += NTHREADS) {
        int v = idx >> 5, o = idx & 31;
        const char* p = smem + v * SLAB_V_B + o * 4;
        float m = *(const float*)p;
        #pragma unroll
        for (int t = 1; t < 16; ++t)
            m = fmaxf(m, *(const float*)(p + t * SLAB_T_B));
        if (v < vlim)
            out[(size_t)(vbase + v) * 32 + o] = m;
    }
}

extern "C" void kernel_launch(void* const* d_in, const int* in_sizes, int n_in,
                              void* d_out, int out_size)
{
    const float* x    = (const float*)d_in[0];
    const int*   cidx = (const int*)  d_in[1];
    const float* cval = (const float*)d_in[2];
    const float* wts  = (const float*)d_in[3];
    float* out = (float*)d_out;

    geo_prep_b<<<40, 512>>>(wts);
    geo_gather_kernel<<<(NROWS + RPB - 1) / RPB, K1T>>>(x, cidx, cval);

    cudaFuncSetAttribute(geo_mma_kernel,
                         cudaFuncAttributeMaxDynamicSharedMemorySize, SMEM_TOTAL);
    geo_mma_kernel<<<NCTAS, NTHREADS, SMEM_TOTAL>>>(out);
}

// round 11
// speedup vs baseline: 2.2478x; 1.0418x over previous
#include <cuda_runtime.h>
#include <cuda_bf16.h>
#include <cstdint>

// GeodesicLayer, three-kernel split (persistent GEMM):
//  K0: W -> bf16 hi/lo padded Bt[n][k] in gmem; also resets the tile counter.
//  K1: h[v,b,i] = sum_k conn_val*x[conn_idx] -> gmem bf16 hi/lo [30016][1280]
//  K2: persistent CTAs (1/SM), B in smem once, dynamic MTILE=32 tile queue,
//      mma.sync bf16 3-term split, cp.async 3-stage A pipeline,
//      max over t via 4-step warp-pair smem reduction tree.

#define NVERT 30000
#define NVPAD 30016
#define KTOT  1280
#define NROWS (NVERT * 80)                     // 2,400,000

#define BT_STRIDE_EL 1288

__device__ __nv_bfloat16 g_hhi[(size_t)NVPAD * KTOT];
__device__ __nv_bfloat16 g_hlo[(size_t)NVPAD * KTOT];
__device__ __nv_bfloat16 g_bt[2 * 32 * BT_STRIDE_EL];   // hi then lo
__device__ int g_ctr;

typedef unsigned int u32;

__device__ __forceinline__ u32 s2u(const void* p) {
    u32 a;
    asm("{ .reg .u64 t; cvta.to.shared.u64 t, %1; cvt.u32.u64 %0, t; }"
        : "=r"(a) : "l"(p));
    return a;
}
__device__ __forceinline__ u32 packbf(float fhi, float flo) {
    u32 r;
    asm("cvt.rn.bf16x2.f32 %0, %1, %2;" : "=r"(r) : "f"(fhi), "f"(flo));
    return r;
}

// ====================== kernel 0: prep B + counter reset ======================
__global__ __launch_bounds__(512)
void geo_prep_b(const float* __restrict__ wts)
{
    if (blockIdx.x == 0 && threadIdx.x == 0) g_ctr = 0;
    const int i0 = blockIdx.x * 1024 + threadIdx.x;
    #pragma unroll
    for (int rep = 0; rep < 2; ++rep) {
        int idx = i0 + rep * 512;             // 0..40959
        float w = wts[idx];
        int k = idx >> 5, n = idx & 31;
        __nv_bfloat16 hi = __float2bfloat16(w);
        __nv_bfloat16 lo = __float2bfloat16(w - __bfloat162float(hi));
        g_bt[n * BT_STRIDE_EL + k] = hi;
        g_bt[32 * BT_STRIDE_EL + n * BT_STRIDE_EL + k] = lo;
    }
}

// ====================== kernel 1: gather ======================
#define RPB 512
#define K1T 256

__global__ __launch_bounds__(K1T)
void geo_gather_kernel(const float* __restrict__ x,
                       const int*   __restrict__ cidx,
                       const float* __restrict__ cval)
{
    __shared__ int   s_idx[RPB * 3];
    __shared__ float s_val[RPB * 3];
    const int tid  = threadIdx.x;
    const long base = (long)blockIdx.x * RPB;

    {
        const int vrows = (int)min((long)RPB, (long)NROWS - base);
        const int vb = vrows * 12;
        const char* si = (const char*)(cidx + base * 3);
        const char* sv = (const char*)(cval + base * 3);
        const u32 di = s2u(s_idx), dv = s2u(s_val);
        for (int q = tid; q < 384; q += K1T) {
            int sz = (q * 16 + 16 <= vb) ? 16 : 0;
            asm volatile("cp.async.cg.shared.global [%0], [%1], 16, %2;"
                         :: "r"(di + q * 16), "l"(si + q * 16), "r"(sz) : "memory");
            asm volatile("cp.async.cg.shared.global [%0], [%1], 16, %2;"
                         :: "r"(dv + q * 16), "l"(sv + q * 16), "r"(sz) : "memory");
        }
        asm volatile("cp.async.commit_group;" ::: "memory");
        asm volatile("cp.async.wait_group 0;" ::: "memory");
        __syncthreads();
    }

    const float4* xp = (const float4*)x;
    uint4* dh = (uint4*)g_hhi;
    uint4* dl = (uint4*)g_hlo;

    #pragma unroll
    for (int rr = 0; rr < 2; ++rr) {
        const long grow = base + 2 * tid + rr;
        if (grow < NROWS) {
            const int lr = 2 * tid + rr;
            const int i0 = s_idx[lr * 3], i1 = s_idx[lr * 3 + 1], i2 = s_idx[lr * 3 + 2];
            const float v0 = s_val[lr * 3], v1 = s_val[lr * 3 + 1], v2 = s_val[lr * 3 + 2];
            float4 h4[4];
            #pragma unroll
            for (int j = 0; j < 4; ++j) {
                float4 a = xp[i0 * 4 + j];
                float4 b = xp[i1 * 4 + j];
                float4 c = xp[i2 * 4 + j];
                h4[j].x = v0 * a.x + v1 * b.x + v2 * c.x;
                h4[j].y = v0 * a.y + v1 * b.y + v2 * c.y;
                h4[j].z = v0 * a.z + v1 * b.z + v2 * c.z;
                h4[j].w = v0 * a.w + v1 * b.w + v2 * c.w;
            }
            const float* f = (const float*)h4;
            u32 hi[8], lo[8];
            #pragma unroll
            for (int p = 0; p < 8; ++p) {
                float f0 = f[2 * p], f1 = f[2 * p + 1];
                u32 hp = packbf(f1, f0);
                float g0 = __uint_as_float(hp << 16);
                float g1 = __uint_as_float(hp & 0xffff0000u);
                hi[p] = hp;
                lo[p] = packbf(f1 - g1, f0 - g0);
            }
            dh[grow * 2]     = make_uint4(hi[0], hi[1], hi[2], hi[3]);
            dh[grow * 2 + 1] = make_uint4(hi[4], hi[5], hi[6], hi[7]);
            dl[grow * 2]     = make_uint4(lo[0], lo[1], lo[2], lo[3]);
            dl[grow * 2 + 1] = make_uint4(lo[4], lo[5], lo[6], lo[7]);
        }
    }
}

// ====================== kernel 2: persistent GEMM + max ======================
#define MTILE    32
#define NTILES   (NVPAD / MTILE)               // 938
#define NTHREADS 512
#define GRID_K2  152                           // GB300 SM count

#define BT_BYTES     (32 * BT_STRIDE_EL * 2)   // 82432
#define OFF_BHI      0
#define OFF_BLO      BT_BYTES
#define OFF_A        (2 * BT_BYTES)            // 164864
#define A_ROW_B      144
#define A_HI_BYTES   (MTILE * A_ROW_B)         // 4608
#define A_STAGE      (2 * A_HI_BYTES)          // 9216
#define NSTAGES      3
#define OFF_NEXT     (OFF_A + NSTAGES * A_STAGE)   // 192512
#define OFF_SLAB     (OFF_NEXT + 16)               // 192528
#define SLAB_V_B     136
#define SLAB_BYTES   (MTILE * SLAB_V_B)            // 4352
#define SMEM_TOTAL   (OFF_SLAB + 8 * SLAB_BYTES)   // 227344

__device__ __forceinline__ void ldsm4(u32& r0, u32& r1, u32& r2, u32& r3, u32 addr) {
    asm volatile("ldmatrix.sync.aligned.m8n8.x4.shared.b16 {%0,%1,%2,%3}, [%4];"
        : "=r"(r0), "=r"(r1), "=r"(r2), "=r"(r3) : "r"(addr));
}
__device__ __forceinline__ void mma_bf16(float* d, const u32* a, u32 b0, u32 b1) {
    asm volatile(
        "mma.sync.aligned.m16n8k16.row.col.f32.bf16.bf16.f32 "
        "{%0,%1,%2,%3}, {%4,%5,%6,%7}, {%8,%9}, {%0,%1,%2,%3};"
        : "+f"(d[0]), "+f"(d[1]), "+f"(d[2]), "+f"(d[3])
        : "r"(a[0]), "r"(a[1]), "r"(a[2]), "r"(a[3]), "r"(b0), "r"(b1));
}
__device__ __forceinline__ void cp16(u32 dst, const void* src) {
    asm volatile("cp.async.cg.shared.global [%0], [%1], 16;"
                 :: "r"(dst), "l"(src) : "memory");
}

// copy A chunk c (k = c*64..c*64+63) into stage s: exactly 1 cp.async/thread
__device__ __forceinline__ void issue_copy(int c, int s, u32 sb, int vbase, int tid)
{
    const int arr = tid >> 8;              // 0 = hi, 1 = lo
    const int row = (tid >> 3) & 31;
    const int q   = tid & 7;
    const __nv_bfloat16* src = (arr ? g_hlo : g_hhi)
        + (size_t)(vbase + row) * KTOT + c * 64 + q * 8;
    const u32 dst = sb + OFF_A + s * A_STAGE + arr * A_HI_BYTES
                  + row * A_ROW_B + q * 16;
    cp16(dst, src);
}

__global__ __launch_bounds__(NTHREADS, 1)
void geo_mma_kernel(float* __restrict__ out)
{
    extern __shared__ char smem[];
    const u32 sb   = s2u(smem);
    const int tid  = threadIdx.x;
    const int warp = tid >> 5;             // == t value
    const int lane = tid & 31;

    // ---- load B once (group 0) ----
    {
        const char* src = (const char*)g_bt;
        for (int q = tid; q < BT_BYTES * 2 / 16; q += NTHREADS)
            cp16(sb + q * 16, src + q * 16);
        asm volatile("cp.async.commit_group;" ::: "memory");
    }

    // ldmatrix lane addressing (validated round 8)
    const u32 a_lane = (u32)(((lane & 7) + ((lane >> 3) & 1) * 8) * A_ROW_B
                             + ((lane >> 4) & 1) * 16);
    const u32 b_row  = (u32)((lane & 7) + ((lane >> 4) & 1) * 8);
    const u32 b_lane = b_row * (BT_STRIDE_EL * 2) + (u32)(((lane >> 3) & 1) * 16);
    const u32 bhibase = sb + OFF_BHI;
    const u32 blobase = sb + OFF_BLO;
    int* s_next = (int*)(smem + OFF_NEXT);

    int tile;
    if (tid == 0) *s_next = atomicAdd(&g_ctr, 1);
    __syncthreads();
    tile = *s_next;

    while (tile < NTILES) {
        const int vbase = tile * MTILE;

        float acc[2][4][4];
        #pragma unroll
        for (int m = 0; m < 2; ++m)
            #pragma unroll
            for (int n = 0; n < 4; ++n)
                #pragma unroll
                for (int q = 0; q < 4; ++q) acc[m][n][q] = 0.f;

        issue_copy(0, 0, sb, vbase, tid);
        asm volatile("cp.async.commit_group;" ::: "memory");
        issue_copy(1, 1, sb, vbase, tid);
        asm volatile("cp.async.commit_group;" ::: "memory");

        for (int c = 0; c < 20; ++c) {
            const int s = c % NSTAGES;
            asm volatile("cp.async.wait_group 1;" ::: "memory");
            __syncthreads();               // chunk c visible; stage (c-1)%3 free

            if (c + 2 < 20)
                issue_copy(c + 2, (c + 2) % NSTAGES, sb, vbase, tid);
            asm volatile("cp.async.commit_group;" ::: "memory");

            const u32 abase = sb + OFF_A + s * A_STAGE;
            int wbin = (4 * c + 5 * warp) % 80;

            #pragma unroll
            for (int j = 0; j < 4; ++j) {
                const u32 boff = b_lane + (u32)wbin * 32;
                u32 bh[2][4], bl[2][4];
                ldsm4(bh[0][0], bh[0][1], bh[0][2], bh[0][3], bhibase + boff);
                ldsm4(bh[1][0], bh[1][1], bh[1][2], bh[1][3],
                      bhibase + boff + 16 * BT_STRIDE_EL * 2);
                ldsm4(bl[0][0], bl[0][1], bl[0][2], bl[0][3], blobase + boff);
                ldsm4(bl[1][0], bl[1][1], bl[1][2], bl[1][3],
                      blobase + boff + 16 * BT_STRIDE_EL * 2);

                #pragma unroll
                for (int mt = 0; mt < 2; ++mt) {
                    const u32 aaddr = abase + (u32)(mt * 16 * A_ROW_B + j * 32) + a_lane;
                    u32 ah[4], al[4];
                    ldsm4(ah[0], ah[1], ah[2], ah[3], aaddr);
                    ldsm4(al[0], al[1], al[2], al[3], aaddr + A_HI_BYTES);
                    #pragma unroll
                    for (int nt = 0; nt < 4; ++nt)
                        mma_bf16(acc[mt][nt], ah,
                                 bh[nt >> 1][(nt & 1) * 2], bh[nt >> 1][(nt & 1) * 2 + 1]);
                    #pragma unroll
                    for (int nt = 0; nt < 4; ++nt)
                        mma_bf16(acc[mt][nt], ah,
                                 bl[nt >> 1][(nt & 1) * 2], bl[nt >> 1][(nt & 1) * 2 + 1]);
                    #pragma unroll
                    for (int nt = 0; nt < 4; ++nt)
                        mma_bf16(acc[mt][nt], al,
                                 bh[nt >> 1][(nt & 1) * 2], bh[nt >> 1][(nt & 1) * 2 + 1]);
                }
                ++wbin; if (wbin == 80) wbin = 0;
            }
        }

        // ---- fetch next tile + max-over-t reduction tree ----
        if (tid == 0) *s_next = atomicAdd(&g_ctr, 1);

        #pragma unroll
        for (int k = 8; k >= 1; k >>= 1) {
            if (warp >= k && warp < 2 * k) {
                char* sl = smem + OFF_SLAB + (warp - k) * SLAB_BYTES;
                #pragma unroll
                for (int mt = 0; mt < 2; ++mt)
                    #pragma unroll
                    for (int nt = 0; nt < 4; ++nt) {
                        int v = mt * 16 + (lane >> 2);
                        u32 ob = (u32)((nt * 8 + (lane & 3) * 2) * 4);
                        *(float2*)(sl + v * SLAB_V_B + ob) =
                            make_float2(acc[mt][nt][0], acc[mt][nt][1]);
                        *(float2*)(sl + (v + 8) * SLAB_V_B + ob) =
                            make_float2(acc[mt][nt][2], acc[mt][nt][3]);
                    }
            }
            __syncthreads();
            if (warp < k) {
                const char* sl = smem + OFF_SLAB + warp * SLAB_BYTES;
                #pragma unroll
                for (int mt = 0; mt < 2; ++mt)
                    #pragma unroll
                    for (int nt = 0; nt < 4; ++nt) {
                        int v = mt * 16 + (lane >> 2);
                        u32 ob = (u32)((nt * 8 + (lane & 3) * 2) * 4);
                        float2 p0 = *(const float2*)(sl + v * SLAB_V_B + ob);
                        float2 p1 = *(const float2*)(sl + (v + 8) * SLAB_V_B + ob);
                        acc[mt][nt][0] = fmaxf(acc[mt][nt][0], p0.x);
                        acc[mt][nt][1] = fmaxf(acc[mt][nt][1], p0.y);
                        acc[mt][nt][2] = fmaxf(acc[mt][nt][2], p1.x);
                        acc[mt][nt][3] = fmaxf(acc[mt][nt][3], p1.y);
                    }
            }
            __syncthreads();
        }

        if (warp == 0) {
            #pragma unroll
            for (int mt = 0; mt < 2; ++mt)
                #pragma unroll
                for (int nt = 0; nt < 4; ++nt) {
                    int v = mt * 16 + (lane >> 2);
                    int o = nt * 8 + (lane & 3) * 2;
                    if (vbase + v < NVERT)
                        *(float2*)(out + (size_t)(vbase + v) * 32 + o) =
                            make_float2(acc[mt][nt][0], acc[mt][nt][1]);
                    if (vbase + v + 8 < NVERT)
                        *(float2*)(out + (size_t)(vbase + v + 8) * 32 + o) =
                            make_float2(acc[mt][nt][2], acc[mt][nt][3]);
                }
        }
        tile = *s_next;      // safe: both syncs above ordered tid0's write
    }
}

extern "C" void kernel_launch(void* const* d_in, const int* in_sizes, int n_in,
                              void* d_out, int out_size)
{
    const float* x    = (const float*)d_in[0];
    const int*   cidx = (const int*)  d_in[1];
    const float* cval = (const float*)d_in[2];
    const float* wts  = (const float*)d_in[3];
    float* out = (float*)d_out;

    geo_prep_b<<<40, 512>>>(wts);
    geo_gather_kernel<<<(NROWS + RPB - 1) / RPB, K1T>>>(x, cidx, cval);

    cudaFuncSetAttribute(geo_mma_kernel,
                         cudaFuncAttributeMaxDynamicSharedMemorySize, SMEM_TOTAL);
    geo_mma_kernel<<<GRID_K2, NTHREADS, SMEM_TOTAL>>>(out);
}

// round 12
// speedup vs baseline: 2.3273x; 1.0353x over previous
#include <cuda_runtime.h>
#include <cuda_bf16.h>
#include <cstdint>

// GeodesicLayer, four-kernel split (persistent GEMM, flat chunk pipeline):
//  K0: W -> bf16 hi/lo padded Bt[n][k] in gmem; resets tile counter.
//  K1: h[v,b,i] = sum_k conn_val*x[conn_idx] -> gmem bf16 hi/lo [30016][1280]
//  K2: persistent CTAs (1/SM), B in smem once, dynamic MTILE=32 tile queue,
//      mma.sync bf16 3-term split, cp.async 3-stage pipeline over ABSOLUTE
//      chunk indices (prefetch crosses tile boundaries), per-warp t-slab STG.
//  K3: out[n,o] = max_t g_part[t][n][o]   (pure HBM stream)

#define NVERT 30000
#define NVPAD 30016
#define KTOT  1280
#define NROWS (NVERT * 80)                     // 2,400,000

#define BT_STRIDE_EL 1288

__device__ __nv_bfloat16 g_hhi[(size_t)NVPAD * KTOT];
__device__ __nv_bfloat16 g_hlo[(size_t)NVPAD * KTOT];
__device__ __nv_bfloat16 g_bt[2 * 32 * BT_STRIDE_EL];   // hi then lo
__device__ float g_part[(size_t)16 * NVPAD * 32];       // [t][n][o]
__device__ int g_ctr;

typedef unsigned int u32;

__device__ __forceinline__ u32 s2u(const void* p) {
    u32 a;
    asm("{ .reg .u64 t; cvta.to.shared.u64 t, %1; cvt.u32.u64 %0, t; }"
        : "=r"(a) : "l"(p));
    return a;
}
__device__ __forceinline__ u32 packbf(float fhi, float flo) {
    u32 r;
    asm("cvt.rn.bf16x2.f32 %0, %1, %2;" : "=r"(r) : "f"(fhi), "f"(flo));
    return r;
}

// ====================== kernel 0: prep B + counter reset ======================
__global__ __launch_bounds__(512)
void geo_prep_b(const float* __restrict__ wts)
{
    if (blockIdx.x == 0 && threadIdx.x == 0) g_ctr = 0;
    const int i0 = blockIdx.x * 1024 + threadIdx.x;
    #pragma unroll
    for (int rep = 0; rep < 2; ++rep) {
        int idx = i0 + rep * 512;             // 0..40959
        float w = wts[idx];
        int k = idx >> 5, n = idx & 31;
        __nv_bfloat16 hi = __float2bfloat16(w);
        __nv_bfloat16 lo = __float2bfloat16(w - __bfloat162float(hi));
        g_bt[n * BT_STRIDE_EL + k] = hi;
        g_bt[32 * BT_STRIDE_EL + n * BT_STRIDE_EL + k] = lo;
    }
}

// ====================== kernel 1: gather ======================
#define RPB 512
#define K1T 256

__global__ __launch_bounds__(K1T)
void geo_gather_kernel(const float* __restrict__ x,
                       const int*   __restrict__ cidx,
                       const float* __restrict__ cval)
{
    __shared__ int   s_idx[RPB * 3];
    __shared__ float s_val[RPB * 3];
    const int tid  = threadIdx.x;
    const long base = (long)blockIdx.x * RPB;

    {
        const int vrows = (int)min((long)RPB, (long)NROWS - base);
        const int vb = vrows * 12;
        const char* si = (const char*)(cidx + base * 3);
        const char* sv = (const char*)(cval + base * 3);
        const u32 di = s2u(s_idx), dv = s2u(s_val);
        for (int q = tid; q < 384; q += K1T) {
            int sz = (q * 16 + 16 <= vb) ? 16 : 0;
            asm volatile("cp.async.cg.shared.global [%0], [%1], 16, %2;"
                         :: "r"(di + q * 16), "l"(si + q * 16), "r"(sz) : "memory");
            asm volatile("cp.async.cg.shared.global [%0], [%1], 16, %2;"
                         :: "r"(dv + q * 16), "l"(sv + q * 16), "r"(sz) : "memory");
        }
        asm volatile("cp.async.commit_group;" ::: "memory");
        asm volatile("cp.async.wait_group 0;" ::: "memory");
        __syncthreads();
    }

    const float4* xp = (const float4*)x;
    uint4* dh = (uint4*)g_hhi;
    uint4* dl = (uint4*)g_hlo;

    #pragma unroll
    for (int rr = 0; rr < 2; ++rr) {
        const long grow = base + 2 * tid + rr;
        if (grow < NROWS) {
            const int lr = 2 * tid + rr;
            const int i0 = s_idx[lr * 3], i1 = s_idx[lr * 3 + 1], i2 = s_idx[lr * 3 + 2];
            const float v0 = s_val[lr * 3], v1 = s_val[lr * 3 + 1], v2 = s_val[lr * 3 + 2];
            float4 h4[4];
            #pragma unroll
            for (int j = 0; j < 4; ++j) {
                float4 a = xp[i0 * 4 + j];
                float4 b = xp[i1 * 4 + j];
                float4 c = xp[i2 * 4 + j];
                h4[j].x = v0 * a.x + v1 * b.x + v2 * c.x;
                h4[j].y = v0 * a.y + v1 * b.y + v2 * c.y;
                h4[j].z = v0 * a.z + v1 * b.z + v2 * c.z;
                h4[j].w = v0 * a.w + v1 * b.w + v2 * c.w;
            }
            const float* f = (const float*)h4;
            u32 hi[8], lo[8];
            #pragma unroll
            for (int p = 0; p < 8; ++p) {
                float f0 = f[2 * p], f1 = f[2 * p + 1];
                u32 hp = packbf(f1, f0);
                float g0 = __uint_as_float(hp << 16);
                float g1 = __uint_as_float(hp & 0xffff0000u);
                hi[p] = hp;
                lo[p] = packbf(f1 - g1, f0 - g0);
            }
            dh[grow * 2]     = make_uint4(hi[0], hi[1], hi[2], hi[3]);
            dh[grow * 2 + 1] = make_uint4(hi[4], hi[5], hi[6], hi[7]);
            dl[grow * 2]     = make_uint4(lo[0], lo[1], lo[2], lo[3]);
            dl[grow * 2 + 1] = make_uint4(lo[4], lo[5], lo[6], lo[7]);
        }
    }
}

// ====================== kernel 2: persistent GEMM ======================
#define MTILE    32
#define NTILES   (NVPAD / MTILE)               // 938
#define NTHREADS 512
#define GRID_K2  152

#define CHUNKS   10                            // K-chunks of 128 per tile
#define BT_BYTES     (32 * BT_STRIDE_EL * 2)   // 82432
#define OFF_BHI      0
#define OFF_BLO      BT_BYTES
#define OFF_A        (2 * BT_BYTES)            // 164864
#define A_ROW_B      272                       // 128 bf16 = 256 B + 16 pad
#define A_HI_BYTES   (MTILE * A_ROW_B)         // 8704
#define A_STAGE      (2 * A_HI_BYTES)          // 17408
#define NSTAGES      3
#define OFF_NEXT     (OFF_A + NSTAGES * A_STAGE)   // 217088
#define SMEM_TOTAL   (OFF_NEXT + 16)               // 217104

__device__ __forceinline__ void ldsm4(u32& r0, u32& r1, u32& r2, u32& r3, u32 addr) {
    asm volatile("ldmatrix.sync.aligned.m8n8.x4.shared.b16 {%0,%1,%2,%3}, [%4];"
        : "=r"(r0), "=r"(r1), "=r"(r2), "=r"(r3) : "r"(addr));
}
__device__ __forceinline__ void mma_bf16(float* d, const u32* a, u32 b0, u32 b1) {
    asm volatile(
        "mma.sync.aligned.m16n8k16.row.col.f32.bf16.bf16.f32 "
        "{%0,%1,%2,%3}, {%4,%5,%6,%7}, {%8,%9}, {%0,%1,%2,%3};"
        : "+f"(d[0]), "+f"(d[1]), "+f"(d[2]), "+f"(d[3])
        : "r"(a[0]), "r"(a[1]), "r"(a[2]), "r"(a[3]), "r"(b0), "r"(b1));
}
__device__ __forceinline__ void cp16(u32 dst, const void* src) {
    asm volatile("cp.async.cg.shared.global [%0], [%1], 16;"
                 :: "r"(dst), "l"(src) : "memory");
}

// copy A chunk c (k = c*128 .. c*128+127) of tile `tl` into stage s:
// 2 cp.async per thread (1024 16B pieces, 512 threads)
__device__ __forceinline__ void issue_copy(int tl, int c, int s, u32 sb, int tid)
{
    const int arr = tid >> 8;              // 0 = hi, 1 = lo
    const int row = (tid >> 3) & 31;
    const int q   = tid & 7;
    const __nv_bfloat16* src = (arr ? g_hlo : g_hhi)
        + (size_t)(tl * MTILE + row) * KTOT + c * 128 + q * 8;
    const u32 dst = sb + OFF_A + s * A_STAGE + arr * A_HI_BYTES
                  + row * A_ROW_B + q * 16;
    cp16(dst, src);
    cp16(dst + 128, src + 64);
}

__global__ __launch_bounds__(NTHREADS, 1)
void geo_mma_kernel()
{
    extern __shared__ char smem[];
    const u32 sb   = s2u(smem);
    const int tid  = threadIdx.x;
    const int warp = tid >> 5;             // == t value
    const int lane = tid & 31;

    // ---- load B once (group 0) ----
    {
        const char* src = (const char*)g_bt;
        for (int q = tid; q < BT_BYTES * 2 / 16; q += NTHREADS)
            cp16(sb + q * 16, src + q * 16);
        asm volatile("cp.async.commit_group;" ::: "memory");
    }

    // ldmatrix lane addressing (validated round 8)
    const u32 a_lane = (u32)(((lane & 7) + ((lane >> 3) & 1) * 8) * A_ROW_B
                             + ((lane >> 4) & 1) * 16);
    const u32 b_row  = (u32)((lane & 7) + ((lane >> 4) & 1) * 8);
    const u32 b_lane = b_row * (BT_STRIDE_EL * 2) + (u32)(((lane >> 3) & 1) * 16);
    const u32 bhibase = sb + OFF_BHI;
    const u32 blobase = sb + OFF_BLO;
    int* s_next = (int*)(smem + OFF_NEXT);

    // first tile id
    if (tid == 0) *s_next = atomicAdd(&g_ctr, 1);
    __syncthreads();
    int tile = *s_next;

    // prime pipeline: chunks 0,1 of first tile
    if (tile < NTILES) issue_copy(tile, 0, 0, sb, tid);
    asm volatile("cp.async.commit_group;" ::: "memory");
    if (tile < NTILES) issue_copy(tile, 1, 1, sb, tid);
    asm volatile("cp.async.commit_group;" ::: "memory");

    int ist = 2;    // stage for next issued chunk
    int cst = 0;    // stage of chunk being consumed

    while (tile < NTILES) {
        const int vbase = tile * MTILE;

        float acc[2][4][4];
        #pragma unroll
        for (int m = 0; m < 2; ++m)
            #pragma unroll
            for (int n = 0; n < 4; ++n)
                #pragma unroll
                for (int q = 0; q < 4; ++q) acc[m][n][q] = 0.f;

        for (int c = 0; c < CHUNKS; ++c) {
            asm volatile("cp.async.wait_group 1;" ::: "memory");
            __syncthreads();               // chunk c visible; stage ist free

            if (c == 0 && tid == 0) *s_next = atomicAdd(&g_ctr, 1);

            // prefetch chunk c+2 (may belong to next tile; s_next is readable
            // for c>=1 thanks to the per-chunk syncthreads)
            {
                int pt = tile, pc = c + 2;
                if (pc >= CHUNKS) { pt = *s_next; pc -= CHUNKS; }
                if (pt < NTILES) issue_copy(pt, pc, ist, sb, tid);
                asm volatile("cp.async.commit_group;" ::: "memory");
                ist = (ist + 1 == NSTAGES) ? 0 : ist + 1;
            }

            const u32 abase = sb + OFF_A + cst * A_STAGE;
            cst = (cst + 1 == NSTAGES) ? 0 : cst + 1;
            int wbin = (8 * c + 5 * warp) % 80;

            #pragma unroll
            for (int j = 0; j < 8; ++j) {
                const u32 boff = b_lane + (u32)wbin * 32;
                u32 bh[2][4], bl[2][4];
                ldsm4(bh[0][0], bh[0][1], bh[0][2], bh[0][3], bhibase + boff);
                ldsm4(bh[1][0], bh[1][1], bh[1][2], bh[1][3],
                      bhibase + boff + 16 * BT_STRIDE_EL * 2);
                ldsm4(bl[0][0], bl[0][1], bl[0][2], bl[0][3], blobase + boff);
                ldsm4(bl[1][0], bl[1][1], bl[1][2], bl[1][3],
                      blobase + boff + 16 * BT_STRIDE_EL * 2);

                #pragma unroll
                for (int mt = 0; mt < 2; ++mt) {
                    const u32 aaddr = abase + (u32)(mt * 16 * A_ROW_B + j * 32) + a_lane;
                    u32 ah[4], al[4];
                    ldsm4(ah[0], ah[1], ah[2], ah[3], aaddr);
                    ldsm4(al[0], al[1], al[2], al[3], aaddr + A_HI_BYTES);
                    #pragma unroll
                    for (int nt = 0; nt < 4; ++nt)
                        mma_bf16(acc[mt][nt], ah,
                                 bh[nt >> 1][(nt & 1) * 2], bh[nt >> 1][(nt & 1) * 2 + 1]);
                    #pragma unroll
                    for (int nt = 0; nt < 4; ++nt)
                        mma_bf16(acc[mt][nt], ah,
                                 bl[nt >> 1][(nt & 1) * 2], bl[nt >> 1][(nt & 1) * 2 + 1]);
                    #pragma unroll
                    for (int nt = 0; nt < 4; ++nt)
                        mma_bf16(acc[mt][nt], al,
                                 bh[nt >> 1][(nt & 1) * 2], bh[nt >> 1][(nt & 1) * 2 + 1]);
                }
                ++wbin; if (wbin == 80) wbin = 0;
            }
        }

        // ---- epilogue: STG this warp's t-slab (no barrier needed) ----
        {
            float* basep = g_part + ((size_t)warp * NVPAD + vbase) * 32;
            #pragma unroll
            for (int mt = 0; mt < 2; ++mt)
                #pragma unroll
                for (int nt = 0; nt < 4; ++nt) {
                    int v = mt * 16 + (lane >> 2);
                    int o = nt * 8 + (lane & 3) * 2;
                    *(float2*)(basep + v * 32 + o) =
                        make_float2(acc[mt][nt][0], acc[mt][nt][1]);
                    *(float2*)(basep + (v + 8) * 32 + o) =
                        make_float2(acc[mt][nt][2], acc[mt][nt][3]);
                }
        }
        tile = *s_next;   // written at c==0, ordered by chunk syncs since
    }
}

// ====================== kernel 3: max over t ======================
__global__ __launch_bounds__(256)
void geo_max_kernel(float* __restrict__ out)
{
    const int idx = blockIdx.x * 256 + threadIdx.x;     // float4 index
    if (idx >= NVERT * 8) return;
    const float4* p = (const float4*)g_part;
    float4 m = p[idx];
    #pragma unroll
    for (int t = 1; t < 16; ++t) {
        float4 v = p[(size_t)t * NVPAD * 8 + idx];
        m.x = fmaxf(m.x, v.x);
        m.y = fmaxf(m.y, v.y);
        m.z = fmaxf(m.z, v.z);
        m.w = fmaxf(m.w, v.w);
    }
    ((float4*)out)[idx] = m;
}

extern "C" void kernel_launch(void* const* d_in, const int* in_sizes, int n_in,
                              void* d_out, int out_size)
{
    const float* x    = (const float*)d_in[0];
    const int*   cidx = (const int*)  d_in[1];
    const float* cval = (const float*)d_in[2];
    const float* wts  = (const float*)d_in[3];
    float* out = (float*)d_out;

    geo_prep_b<<<40, 512>>>(wts);
    geo_gather_kernel<<<(NROWS + RPB - 1) / RPB, K1T>>>(x, cidx, cval);

    cudaFuncSetAttribute(geo_mma_kernel,
                         cudaFuncAttributeMaxDynamicSharedMemorySize, SMEM_TOTAL);
    geo_mma_kernel<<<GRID_K2, NTHREADS, SMEM_TOTAL>>>();

    geo_max_kernel<<<(NVERT * 8 + 255) / 256, 256>>>(out);
}

// round 14
// speedup vs baseline: 2.8302x; 1.2161x over previous
#include <cuda_runtime.h>
#include <cuda_fp16.h>
#include <cstdint>

// GeodesicLayer, four-kernel split (persistent GEMM, fp16 2-term split):
//  K0: W -> fp16 padded Bt[n][k] in gmem; resets tile counter.
//  K1: h[v,b,i] -> gmem fp16 hi + fp16 residual [30016][1280]
//  K2: persistent CTAs, B in smem once, dynamic MTILE=64 tile queue,
//      mma.sync fp16 2-term split (A2*B2 + Ar*B2), cp.async 4-stage pipeline
//      over absolute chunk indices, per-warp t-slab STG to g_part.
//  K3: out[n,o] = max_t g_part[t][n][o]

#define NVERT 30000
#define NVPAD 30016
#define KTOT  1280
#define NROWS (NVERT * 80)                     // 2,400,000

#define BT_STRIDE_EL 1288

__device__ __half g_hhi[(size_t)NVPAD * KTOT];
__device__ __half g_hlo[(size_t)NVPAD * KTOT];
__device__ __half g_bt[32 * BT_STRIDE_EL];
__device__ float g_part[(size_t)16 * NVPAD * 32];       // [t][n][o]
__device__ int g_ctr;

typedef unsigned int u32;

__device__ __forceinline__ u32 s2u(const void* p) {
    u32 a;
    asm("{ .reg .u64 t; cvta.to.shared.u64 t, %1; cvt.u32.u64 %0, t; }"
        : "=r"(a) : "l"(p));
    return a;
}

// ====================== kernel 0: prep B + counter reset ======================
__global__ __launch_bounds__(512)
void geo_prep_b(const float* __restrict__ wts)
{
    if (blockIdx.x == 0 && threadIdx.x == 0) g_ctr = 0;
    const int i0 = blockIdx.x * 1024 + threadIdx.x;
    #pragma unroll
    for (int rep = 0; rep < 2; ++rep) {
        int idx = i0 + rep * 512;             // 0..40959
        float w = wts[idx];
        int k = idx >> 5, n = idx & 31;
        g_bt[n * BT_STRIDE_EL + k] = __float2half_rn(w);
    }
}

// ====================== kernel 1: gather ======================
#define RPB 512
#define K1T 256

__global__ __launch_bounds__(K1T)
void geo_gather_kernel(const float* __restrict__ x,
                       const int*   __restrict__ cidx,
                       const float* __restrict__ cval)
{
    __shared__ int   s_idx[RPB * 3];
    __shared__ float s_val[RPB * 3];
    const int tid  = threadIdx.x;
    const long base = (long)blockIdx.x * RPB;

    {
        const int vrows = (int)min((long)RPB, (long)NROWS - base);
        const int vb = vrows * 12;
        const char* si = (const char*)(cidx + base * 3);
        const char* sv = (const char*)(cval + base * 3);
        const u32 di = s2u(s_idx), dv = s2u(s_val);
        for (int q = tid; q < 384; q += K1T) {
            int sz = (q * 16 + 16 <= vb) ? 16 : 0;
            asm volatile("cp.async.cg.shared.global [%0], [%1], 16, %2;"
                         :: "r"(di + q * 16), "l"(si + q * 16), "r"(sz) : "memory");
            asm volatile("cp.async.cg.shared.global [%0], [%1], 16, %2;"
                         :: "r"(dv + q * 16), "l"(sv + q * 16), "r"(sz) : "memory");
        }
        asm volatile("cp.async.commit_group;" ::: "memory");
        asm volatile("cp.async.wait_group 0;" ::: "memory");
        __syncthreads();
    }

    const float4* xp = (const float4*)x;
    uint4* dh = (uint4*)g_hhi;
    uint4* dl = (uint4*)g_hlo;

    #pragma unroll
    for (int rr = 0; rr < 2; ++rr) {
        const long grow = base + 2 * tid + rr;
        if (grow < NROWS) {
            const int lr = 2 * tid + rr;
            const int i0 = s_idx[lr * 3], i1 = s_idx[lr * 3 + 1], i2 = s_idx[lr * 3 + 2];
            const float v0 = s_val[lr * 3], v1 = s_val[lr * 3 + 1], v2 = s_val[lr * 3 + 2];
            float4 h4[4];
            #pragma unroll
            for (int j = 0; j < 4; ++j) {
                float4 a = xp[i0 * 4 + j];
                float4 b = xp[i1 * 4 + j];
                float4 c = xp[i2 * 4 + j];
                h4[j].x = v0 * a.x + v1 * b.x + v2 * c.x;
                h4[j].y = v0 * a.y + v1 * b.y + v2 * c.y;
                h4[j].z = v0 * a.z + v1 * b.z + v2 * c.z;
                h4[j].w = v0 * a.w + v1 * b.w + v2 * c.w;
            }
            const float* f = (const float*)h4;
            u32 hi[8], lo[8];
            #pragma unroll
            for (int p = 0; p < 8; ++p) {
                float f0 = f[2 * p], f1 = f[2 * p + 1];
                __half2 hh = __floats2half2_rn(f0, f1);
                float2 bk = __half22float2(hh);
                __half2 ll = __floats2half2_rn(f0 - bk.x, f1 - bk.y);
                hi[p] = *(u32*)&hh;
                lo[p] = *(u32*)&ll;
            }
            dh[grow * 2]     = make_uint4(hi[0], hi[1], hi[2], hi[3]);
            dh[grow * 2 + 1] = make_uint4(hi[4], hi[5], hi[6], hi[7]);
            dl[grow * 2]     = make_uint4(lo[0], lo[1], lo[2], lo[3]);
            dl[grow * 2 + 1] = make_uint4(lo[4], lo[5], lo[6], lo[7]);
        }
    }
}

// ====================== kernel 2: persistent GEMM ======================
#define MTILE    64
#define NTILES   (NVPAD / MTILE)               // 469
#define NTHREADS 512
#define GRID_K2  152

#define CHUNKS   10                            // K-chunks of 128 per tile
#define BT_BYTES     (32 * BT_STRIDE_EL * 2)   // 82432 (fp16: 32 rows x 1288 el x 2 B)
#define OFF_A        BT_BYTES                  // 82432 (16B aligned)
#define A_ROW_B      272                       // 128 fp16 = 256 B + 16 pad
#define A_HI_BYTES   (MTILE * A_ROW_B)         // 17408
#define A_STAGE      (2 * A_HI_BYTES)          // 34816 (hi + lo)
#define NSTAGES      4
#define OFF_NEXT     (OFF_A + NSTAGES * A_STAGE)   // 221696
#define SMEM_TOTAL   (OFF_NEXT + 16)               // 221712

__device__ __forceinline__ void ldsm4(u32& r0, u32& r1, u32& r2, u32& r3, u32 addr) {
    asm volatile("ldmatrix.sync.aligned.m8n8.x4.shared.b16 {%0,%1,%2,%3}, [%4];"
        : "=r"(r0), "=r"(r1), "=r"(r2), "=r"(r3) : "r"(addr));
}
__device__ __forceinline__ void mma_f16(float* d, const u32* a, u32 b0, u32 b1) {
    asm volatile(
        "mma.sync.aligned.m16n8k16.row.col.f32.f16.f16.f32 "
        "{%0,%1,%2,%3}, {%4,%5,%6,%7}, {%8,%9}, {%0,%1,%2,%3};"
        : "+f"(d[0]), "+f"(d[1]), "+f"(d[2]), "+f"(d[3])
        : "r"(a[0]), "r"(a[1]), "r"(a[2]), "r"(a[3]), "r"(b0), "r"(b1));
}
__device__ __forceinline__ void cp16(u32 dst, const void* src) {
    asm volatile("cp.async.cg.shared.global [%0], [%1], 16;"
                 :: "r"(dst), "l"(src) : "memory");
}

// copy A chunk c (k = c*128 .. c*128+127) of tile `tl` into stage s:
// 64 rows x 256 B x 2 arrays = 2048 16B pieces, 4 cp.async per thread
__device__ __forceinline__ void issue_copy(int tl, int c, int s, u32 sb, int tid)
{
    const int arr = tid >> 8;              // 0 = hi, 1 = lo
    const int row = (tid >> 2) & 63;
    const int q   = tid & 3;
    const __half* src = (arr ? g_hlo : g_hhi)
        + (size_t)(tl * MTILE + row) * KTOT + c * 128;
    const u32 dst = sb + OFF_A + s * A_STAGE + arr * A_HI_BYTES + row * A_ROW_B;
    #pragma unroll
    for (int u = 0; u < 4; ++u)
        cp16(dst + (q + 4 * u) * 16, src + (q + 4 * u) * 8);
}

__global__ __launch_bounds__(NTHREADS, 1)
void geo_mma_kernel()
{
    extern __shared__ char smem[];
    const u32 sb   = s2u(smem);
    const int tid  = threadIdx.x;
    const int warp = tid >> 5;             // == t value
    const int lane = tid & 31;

    // ---- load B once (group 0): full 82432 bytes ----
    {
        const char* src = (const char*)g_bt;
        for (int q = tid; q < BT_BYTES / 16; q += NTHREADS)
            cp16(sb + q * 16, src + q * 16);
        asm volatile("cp.async.commit_group;" ::: "memory");
    }

    // ldmatrix lane addressing (validated round 8; row strides 272 B and
    // 2576 B are 16B-aligned and phase-distinct mod 128 -> conflict-free)
    const u32 a_lane = (u32)(((lane & 7) + ((lane >> 3) & 1) * 8) * A_ROW_B
                             + ((lane >> 4) & 1) * 16);
    const u32 b_row  = (u32)((lane & 7) + ((lane >> 4) & 1) * 8);
    const u32 b_lane = b_row * (BT_STRIDE_EL * 2) + (u32)(((lane >> 3) & 1) * 16);
    const u32 bbase  = sb;
    int* s_next = (int*)(smem + OFF_NEXT);

    if (tid == 0) *s_next = atomicAdd(&g_ctr, 1);
    __syncthreads();
    int tile = *s_next;

    // prime pipeline: chunks 0,1,2 of first tile
    if (tile < NTILES) issue_copy(tile, 0, 0, sb, tid);
    asm volatile("cp.async.commit_group;" ::: "memory");
    if (tile < NTILES) issue_copy(tile, 1, 1, sb, tid);
    asm volatile("cp.async.commit_group;" ::: "memory");
    if (tile < NTILES) issue_copy(tile, 2, 2, sb, tid);
    asm volatile("cp.async.commit_group;" ::: "memory");

    int ist = 3;    // stage for next issued chunk
    int cst = 0;    // stage of chunk being consumed

    while (tile < NTILES) {
        const int vbase = tile * MTILE;

        float acc[4][4][4];
        #pragma unroll
        for (int m = 0; m < 4; ++m)
            #pragma unroll
            for (int n = 0; n < 4; ++n)
                #pragma unroll
                for (int q = 0; q < 4; ++q) acc[m][n][q] = 0.f;

        for (int c = 0; c < CHUNKS; ++c) {
            asm volatile("cp.async.wait_group 2;" ::: "memory");
            __syncthreads();               // chunk c visible; stage ist free

            if (c == 0 && tid == 0) *s_next = atomicAdd(&g_ctr, 1);

            // prefetch chunk c+3 (may belong to next tile; s_next readable
            // for c>=1 thanks to per-chunk syncthreads)
            {
                int pt = tile, pc = c + 3;
                if (pc >= CHUNKS) { pt = *s_next; pc -= CHUNKS; }
                if (pt < NTILES) issue_copy(pt, pc, ist, sb, tid);
                asm volatile("cp.async.commit_group;" ::: "memory");
                ist = (ist + 1 == NSTAGES) ? 0 : ist + 1;
            }

            const u32 abase = sb + OFF_A + cst * A_STAGE;
            cst = (cst + 1 == NSTAGES) ? 0 : cst + 1;
            int wbin = (8 * c + 5 * warp) % 80;

            #pragma unroll
            for (int j = 0; j < 8; ++j) {
                const u32 boff = b_lane + (u32)wbin * 32;
                u32 bh[2][4];
                ldsm4(bh[0][0], bh[0][1], bh[0][2], bh[0][3], bbase + boff);
                ldsm4(bh[1][0], bh[1][1], bh[1][2], bh[1][3],
                      bbase + boff + 16 * BT_STRIDE_EL * 2);

                #pragma unroll
                for (int mt = 0; mt < 4; ++mt) {
                    const u32 aaddr = abase + (u32)(mt * 16 * A_ROW_B + j * 32) + a_lane;
                    u32 ah[4], al[4];
                    ldsm4(ah[0], ah[1], ah[2], ah[3], aaddr);
                    ldsm4(al[0], al[1], al[2], al[3], aaddr + A_HI_BYTES);
                    #pragma unroll
                    for (int nt = 0; nt < 4; ++nt)
                        mma_f16(acc[mt][nt], ah,
                                bh[nt >> 1][(nt & 1) * 2], bh[nt >> 1][(nt & 1) * 2 + 1]);
                    #pragma unroll
                    for (int nt = 0; nt < 4; ++nt)
                        mma_f16(acc[mt][nt], al,
                                bh[nt >> 1][(nt & 1) * 2], bh[nt >> 1][(nt & 1) * 2 + 1]);
                }
                ++wbin; if (wbin == 80) wbin = 0;
            }
        }

        // ---- epilogue: STG this warp's t-slab (no barrier needed) ----
        {
            float* basep = g_part + ((size_t)warp * NVPAD + vbase) * 32;
            #pragma unroll
            for (int mt = 0; mt < 4; ++mt)
                #pragma unroll
                for (int nt = 0; nt < 4; ++nt) {
                    int v = mt * 16 + (lane >> 2);
                    int o = nt * 8 + (lane & 3) * 2;
                    *(float2*)(basep + v * 32 + o) =
                        make_float2(acc[mt][nt][0], acc[mt][nt][1]);
                    *(float2*)(basep + (v + 8) * 32 + o) =
                        make_float2(acc[mt][nt][2], acc[mt][nt][3]);
                }
        }
        tile = *s_next;   // written at c==0, ordered by chunk syncs since
    }
}

// ====================== kernel 3: max over t ======================
__global__ __launch_bounds__(256)
void geo_max_kernel(float* __restrict__ out)
{
    const int idx = blockIdx.x * 256 + threadIdx.x;     // float4 index
    if (idx >= NVERT * 8) return;
    const float4* p = (const float4*)g_part;
    float4 m = p[idx];
    #pragma unroll
    for (int t = 1; t < 16; ++t) {
        float4 v = p[(size_t)t * NVPAD * 8 + idx];
        m.x = fmaxf(m.x, v.x);
        m.y = fmaxf(m.y, v.y);
        m.z = fmaxf(m.z, v.z);
        m.w = fmaxf(m.w, v.w);
    }
    ((float4*)out)[idx] = m;
}

extern "C" void kernel_launch(void* const* d_in, const int* in_sizes, int n_in,
                              void* d_out, int out_size)
{
    const float* x    = (const float*)d_in[0];
    const int*   cidx = (const int*)  d_in[1];
    const float* cval = (const float*)d_in[2];
    const float* wts  = (const float*)d_in[3];
    float* out = (float*)d_out;

    geo_prep_b<<<40, 512>>>(wts);
    geo_gather_kernel<<<(NROWS + RPB - 1) / RPB, K1T>>>(x, cidx, cval);

    cudaFuncSetAttribute(geo_mma_kernel,
                         cudaFuncAttributeMaxDynamicSharedMemorySize, SMEM_TOTAL);
    geo_mma_kernel<<<GRID_K2, NTHREADS, SMEM_TOTAL>>>();

    geo_max_kernel<<<(NVERT * 8 + 255) / 256, 256>>>(out);
}

// round 15
// speedup vs baseline: 4.0644x; 1.4361x over previous
#include <cuda_runtime.h>
#include <cuda_fp16.h>
#include <cstdint>

// GeodesicLayer, four-kernel split (persistent GEMM, single-term fp16):
//  K0: W -> fp16 padded Bt[n][k] in gmem; resets tile counter.
//  K1: h[v,b,i] -> gmem fp16 [30016][1280]
//  K2: persistent CTAs, B in smem once, dynamic MTILE=64 tile queue,
//      mma.sync fp16 (single term), cp.async 4-stage pipeline, CHUNK_K=256,
//      per-warp t-slab STG to g_part.
//  K3: out[n,o] = max_t g_part[t][n][o]

#define NVERT 30000
#define NVPAD 30016
#define KTOT  1280
#define NROWS (NVERT * 80)                     // 2,400,000

#define BT_STRIDE_EL 1288

__device__ __half g_h[(size_t)NVPAD * KTOT];
__device__ __half g_bt[32 * BT_STRIDE_EL];
__device__ float g_part[(size_t)16 * NVPAD * 32];       // [t][n][o]
__device__ int g_ctr;

typedef unsigned int u32;

__device__ __forceinline__ u32 s2u(const void* p) {
    u32 a;
    asm("{ .reg .u64 t; cvta.to.shared.u64 t, %1; cvt.u32.u64 %0, t; }"
        : "=r"(a) : "l"(p));
    return a;
}

// ====================== kernel 0: prep B + counter reset ======================
__global__ __launch_bounds__(512)
void geo_prep_b(const float* __restrict__ wts)
{
    if (blockIdx.x == 0 && threadIdx.x == 0) g_ctr = 0;
    const int i0 = blockIdx.x * 1024 + threadIdx.x;
    #pragma unroll
    for (int rep = 0; rep < 2; ++rep) {
        int idx = i0 + rep * 512;             // 0..40959
        float w = wts[idx];
        int k = idx >> 5, n = idx & 31;
        g_bt[n * BT_STRIDE_EL + k] = __float2half_rn(w);
    }
}

// ====================== kernel 1: gather ======================
#define RPB 512
#define K1T 256

__global__ __launch_bounds__(K1T)
void geo_gather_kernel(const float* __restrict__ x,
                       const int*   __restrict__ cidx,
                       const float* __restrict__ cval)
{
    __shared__ int   s_idx[RPB * 3];
    __shared__ float s_val[RPB * 3];
    const int tid  = threadIdx.x;
    const long base = (long)blockIdx.x * RPB;

    {
        const int vrows = (int)min((long)RPB, (long)NROWS - base);
        const int vb = vrows * 12;
        const char* si = (const char*)(cidx + base * 3);
        const char* sv = (const char*)(cval + base * 3);
        const u32 di = s2u(s_idx), dv = s2u(s_val);
        for (int q = tid; q < 384; q += K1T) {
            int sz = (q * 16 + 16 <= vb) ? 16 : 0;
            asm volatile("cp.async.cg.shared.global [%0], [%1], 16, %2;"
                         :: "r"(di + q * 16), "l"(si + q * 16), "r"(sz) : "memory");
            asm volatile("cp.async.cg.shared.global [%0], [%1], 16, %2;"
                         :: "r"(dv + q * 16), "l"(sv + q * 16), "r"(sz) : "memory");
        }
        asm volatile("cp.async.commit_group;" ::: "memory");
        asm volatile("cp.async.wait_group 0;" ::: "memory");
        __syncthreads();
    }

    const float4* xp = (const float4*)x;
    uint4* dh = (uint4*)g_h;

    #pragma unroll
    for (int rr = 0; rr < 2; ++rr) {
        const long grow = base + 2 * tid + rr;
        if (grow < NROWS) {
            const int lr = 2 * tid + rr;
            const int i0 = s_idx[lr * 3], i1 = s_idx[lr * 3 + 1], i2 = s_idx[lr * 3 + 2];
            const float v0 = s_val[lr * 3], v1 = s_val[lr * 3 + 1], v2 = s_val[lr * 3 + 2];
            float4 h4[4];
            #pragma unroll
            for (int j = 0; j < 4; ++j) {
                float4 a = xp[i0 * 4 + j];
                float4 b = xp[i1 * 4 + j];
                float4 c = xp[i2 * 4 + j];
                h4[j].x = v0 * a.x + v1 * b.x + v2 * c.x;
                h4[j].y = v0 * a.y + v1 * b.y + v2 * c.y;
                h4[j].z = v0 * a.z + v1 * b.z + v2 * c.z;
                h4[j].w = v0 * a.w + v1 * b.w + v2 * c.w;
            }
            const float* f = (const float*)h4;
            u32 hi[8];
            #pragma unroll
            for (int p = 0; p < 8; ++p) {
                __half2 hh = __floats2half2_rn(f[2 * p], f[2 * p + 1]);
                hi[p] = *(u32*)&hh;
            }
            dh[grow * 2]     = make_uint4(hi[0], hi[1], hi[2], hi[3]);
            dh[grow * 2 + 1] = make_uint4(hi[4], hi[5], hi[6], hi[7]);
        }
    }
}

// ====================== kernel 2: persistent GEMM ======================
#define MTILE    64
#define NTILES   (NVPAD / MTILE)               // 469
#define NTHREADS 512
#define GRID_K2  152

#define CHUNKS   5                             // K-chunks of 256 per tile
#define CHUNK_K  256
#define BT_BYTES     (32 * BT_STRIDE_EL * 2)   // 82432
#define OFF_A        BT_BYTES                  // 82432 (16B aligned)
#define A_ROW_B      528                       // 256 fp16 = 512 B + 16 pad
#define A_STAGE      (MTILE * A_ROW_B)         // 33792
#define NSTAGES      4
#define OFF_NEXT     (OFF_A + NSTAGES * A_STAGE)   // 217600
#define SMEM_TOTAL   (OFF_NEXT + 16)               // 217616

__device__ __forceinline__ void ldsm4(u32& r0, u32& r1, u32& r2, u32& r3, u32 addr) {
    asm volatile("ldmatrix.sync.aligned.m8n8.x4.shared.b16 {%0,%1,%2,%3}, [%4];"
        : "=r"(r0), "=r"(r1), "=r"(r2), "=r"(r3) : "r"(addr));
}
__device__ __forceinline__ void mma_f16(float* d, const u32* a, u32 b0, u32 b1) {
    asm volatile(
        "mma.sync.aligned.m16n8k16.row.col.f32.f16.f16.f32 "
        "{%0,%1,%2,%3}, {%4,%5,%6,%7}, {%8,%9}, {%0,%1,%2,%3};"
        : "+f"(d[0]), "+f"(d[1]), "+f"(d[2]), "+f"(d[3])
        : "r"(a[0]), "r"(a[1]), "r"(a[2]), "r"(a[3]), "r"(b0), "r"(b1));
}
__device__ __forceinline__ void cp16(u32 dst, const void* src) {
    asm volatile("cp.async.cg.shared.global [%0], [%1], 16;"
                 :: "r"(dst), "l"(src) : "memory");
}

// copy A chunk c (k = c*256 .. c*256+255) of tile `tl` into stage s:
// 64 rows x 512 B = 2048 16B pieces, 4 cp.async per thread
__device__ __forceinline__ void issue_copy(int tl, int c, int s, u32 sb, int tid)
{
    const int row = tid >> 3;              // 0..63
    const int q   = tid & 7;
    const __half* src = g_h + (size_t)(tl * MTILE + row) * KTOT + c * CHUNK_K;
    const u32 dst = sb + OFF_A + s * A_STAGE + row * A_ROW_B;
    #pragma unroll
    for (int u = 0; u < 4; ++u)
        cp16(dst + (q + 8 * u) * 16, src + (q + 8 * u) * 8);
}

__global__ __launch_bounds__(NTHREADS, 1)
void geo_mma_kernel()
{
    extern __shared__ char smem[];
    const u32 sb   = s2u(smem);
    const int tid  = threadIdx.x;
    const int warp = tid >> 5;             // == t value
    const int lane = tid & 31;

    // ---- load B once (group 0): full 82432 bytes ----
    {
        const char* src = (const char*)g_bt;
        for (int q = tid; q < BT_BYTES / 16; q += NTHREADS)
            cp16(sb + q * 16, src + q * 16);
        asm volatile("cp.async.commit_group;" ::: "memory");
    }

    // ldmatrix lane addressing (validated round 8; 528 mod 128 = 16 ->
    // 8 rows/phase land on distinct 16B banks, conflict-free)
    const u32 a_lane = (u32)(((lane & 7) + ((lane >> 3) & 1) * 8) * A_ROW_B
                             + ((lane >> 4) & 1) * 16);
    const u32 b_row  = (u32)((lane & 7) + ((lane >> 4) & 1) * 8);
    const u32 b_lane = b_row * (BT_STRIDE_EL * 2) + (u32)(((lane >> 3) & 1) * 16);
    const u32 bbase  = sb;
    int* s_next = (int*)(smem + OFF_NEXT);

    if (tid == 0) *s_next = atomicAdd(&g_ctr, 1);
    __syncthreads();
    int tile = *s_next;

    // prime pipeline: chunks 0,1,2 of first tile
    if (tile < NTILES) issue_copy(tile, 0, 0, sb, tid);
    asm volatile("cp.async.commit_group;" ::: "memory");
    if (tile < NTILES) issue_copy(tile, 1, 1, sb, tid);
    asm volatile("cp.async.commit_group;" ::: "memory");
    if (tile < NTILES) issue_copy(tile, 2, 2, sb, tid);
    asm volatile("cp.async.commit_group;" ::: "memory");

    int ist = 3;    // stage for next issued chunk
    int cst = 0;    // stage of chunk being consumed

    while (tile < NTILES) {
        const int vbase = tile * MTILE;

        float acc[4][4][4];
        #pragma unroll
        for (int m = 0; m < 4; ++m)
            #pragma unroll
            for (int n = 0; n < 4; ++n)
                #pragma unroll
                for (int q = 0; q < 4; ++q) acc[m][n][q] = 0.f;

        for (int c = 0; c < CHUNKS; ++c) {
            asm volatile("cp.async.wait_group 2;" ::: "memory");
            __syncthreads();               // chunk c visible; stage ist free

            if (c == 0 && tid == 0) *s_next = atomicAdd(&g_ctr, 1);

            // prefetch chunk c+3 (may belong to next tile; s_next readable
            // for c>=1 thanks to per-chunk syncthreads)
            {
                int pt = tile, pc = c + 3;
                if (pc >= CHUNKS) { pt = *s_next; pc -= CHUNKS; }
                if (pt < NTILES) issue_copy(pt, pc, ist, sb, tid);
                asm volatile("cp.async.commit_group;" ::: "memory");
                ist = (ist + 1 == NSTAGES) ? 0 : ist + 1;
            }

            const u32 abase = sb + OFF_A + cst * A_STAGE;
            cst = (cst + 1 == NSTAGES) ? 0 : cst + 1;
            int wbin = (16 * c + 5 * warp) % 80;

            #pragma unroll
            for (int j = 0; j < 16; ++j) {
                const u32 boff = b_lane + (u32)wbin * 32;
                u32 bh[2][4];
                ldsm4(bh[0][0], bh[0][1], bh[0][2], bh[0][3], bbase + boff);
                ldsm4(bh[1][0], bh[1][1], bh[1][2], bh[1][3],
                      bbase + boff + 16 * BT_STRIDE_EL * 2);

                #pragma unroll
                for (int mt = 0; mt < 4; ++mt) {
                    const u32 aaddr = abase + (u32)(mt * 16 * A_ROW_B + j * 32) + a_lane;
                    u32 ah[4];
                    ldsm4(ah[0], ah[1], ah[2], ah[3], aaddr);
                    #pragma unroll
                    for (int nt = 0; nt < 4; ++nt)
                        mma_f16(acc[mt][nt], ah,
                                bh[nt >> 1][(nt & 1) * 2], bh[nt >> 1][(nt & 1) * 2 + 1]);
                }
                ++wbin; if (wbin == 80) wbin = 0;
            }
        }

        // ---- epilogue: STG this warp's t-slab (no barrier needed) ----
        {
            float* basep = g_part + ((size_t)warp * NVPAD + vbase) * 32;
            #pragma unroll
            for (int mt = 0; mt < 4; ++mt)
                #pragma unroll
                for (int nt = 0; nt < 4; ++nt) {
                    int v = mt * 16 + (lane >> 2);
                    int o = nt * 8 + (lane & 3) * 2;
                    *(float2*)(basep + v * 32 + o) =
                        make_float2(acc[mt][nt][0], acc[mt][nt][1]);
                    *(float2*)(basep + (v + 8) * 32 + o) =
                        make_float2(acc[mt][nt][2], acc[mt][nt][3]);
                }
        }
        tile = *s_next;   // written at c==0, ordered by chunk syncs since
    }
}

// ====================== kernel 3: max over t ======================
__global__ __launch_bounds__(256)
void geo_max_kernel(float* __restrict__ out)
{
    const int idx = blockIdx.x * 256 + threadIdx.x;     // float4 index
    if (idx >= NVERT * 8) return;
    const float4* p = (const float4*)g_part;
    float4 m = p[idx];
    #pragma unroll
    for (int t = 1; t < 16; ++t) {
        float4 v = p[(size_t)t * NVPAD * 8 + idx];
        m.x = fmaxf(m.x, v.x);
        m.y = fmaxf(m.y, v.y);
        m.z = fmaxf(m.z, v.z);
        m.w = fmaxf(m.w, v.w);
    }
    ((float4*)out)[idx] = m;
}

extern "C" void kernel_launch(void* const* d_in, const int* in_sizes, int n_in,
                              void* d_out, int out_size)
{
    const float* x    = (const float*)d_in[0];
    const int*   cidx = (const int*)  d_in[1];
    const float* cval = (const float*)d_in[2];
    const float* wts  = (const float*)d_in[3];
    float* out = (float*)d_out;

    geo_prep_b<<<40, 512>>>(wts);
    geo_gather_kernel<<<(NROWS + RPB - 1) / RPB, K1T>>>(x, cidx, cval);

    cudaFuncSetAttribute(geo_mma_kernel,
                         cudaFuncAttributeMaxDynamicSharedMemorySize, SMEM_TOTAL);
    geo_mma_kernel<<<GRID_K2, NTHREADS, SMEM_TOTAL>>>();

    geo_max_kernel<<<(NVERT * 8 + 255) / 256, 256>>>(out);
}

// round 16
// speedup vs baseline: 6.2137x; 1.5288x over previous
#include <cuda_runtime.h>
#include <cuda_fp16.h>
#include <cstdint>

// GeodesicLayer, four-kernel split (persistent GEMM, single-term fp16):
//  K0: W -> fp16 padded Bt[n][k] in gmem; resets tile counter.
//  K1: h[v,b,i] -> gmem fp16 [30016][1280]; transposed lanes (8 lanes/row,
//      float2 x loads) for coalesced L1 wavefronts.
//  K2: persistent CTAs, B in smem once, dynamic MTILE=32 tile queue,
//      mma.sync fp16, cp.async 4-stage pipeline, CHUNK_K=256,
//      per-warp t-slab STG to g_part.
//  K3: out[n,o] = max_t g_part[t][n][o]

#define NVERT 30000
#define NVPAD 30016
#define KTOT  1280
#define NROWS (NVERT * 80)                     // 2,400,000

#define BT_STRIDE_EL 1288

__device__ __half g_h[(size_t)NVPAD * KTOT];
__device__ __half g_bt[32 * BT_STRIDE_EL];
__device__ float g_part[(size_t)16 * NVPAD * 32];       // [t][n][o]
__device__ int g_ctr;

typedef unsigned int u32;

__device__ __forceinline__ u32 s2u(const void* p) {
    u32 a;
    asm("{ .reg .u64 t; cvta.to.shared.u64 t, %1; cvt.u32.u64 %0, t; }"
        : "=r"(a) : "l"(p));
    return a;
}

// ====================== kernel 0: prep B + counter reset ======================
__global__ __launch_bounds__(512)
void geo_prep_b(const float* __restrict__ wts)
{
    if (blockIdx.x == 0 && threadIdx.x == 0) g_ctr = 0;
    const int i0 = blockIdx.x * 1024 + threadIdx.x;
    #pragma unroll
    for (int rep = 0; rep < 2; ++rep) {
        int idx = i0 + rep * 512;             // 0..40959
        float w = wts[idx];
        int k = idx >> 5, n = idx & 31;
        g_bt[n * BT_STRIDE_EL + k] = __float2half_rn(w);
    }
}

// ====================== kernel 1: gather (transposed lanes) ======================
#define RPB 512
#define K1T 256

__global__ __launch_bounds__(K1T)
void geo_gather_kernel(const float* __restrict__ x,
                       const int*   __restrict__ cidx,
                       const float* __restrict__ cval)
{
    __shared__ int   s_idx[RPB * 3];
    __shared__ float s_val[RPB * 3];
    const int tid  = threadIdx.x;
    const long base = (long)blockIdx.x * RPB;

    {
        const int vrows = (int)min((long)RPB, (long)NROWS - base);
        const int vb = vrows * 12;
        const char* si = (const char*)(cidx + base * 3);
        const char* sv = (const char*)(cval + base * 3);
        const u32 di = s2u(s_idx), dv = s2u(s_val);
        for (int q = tid; q < 384; q += K1T) {
            int sz = (q * 16 + 16 <= vb) ? 16 : 0;
            asm volatile("cp.async.cg.shared.global [%0], [%1], 16, %2;"
                         :: "r"(di + q * 16), "l"(si + q * 16), "r"(sz) : "memory");
            asm volatile("cp.async.cg.shared.global [%0], [%1], 16, %2;"
                         :: "r"(dv + q * 16), "l"(sv + q * 16), "r"(sz) : "memory");
        }
        asm volatile("cp.async.commit_group;" ::: "memory");
        asm volatile("cp.async.wait_group 0;" ::: "memory");
        __syncthreads();
    }

    // 8 lanes per conn row, each lane owns 2 channels (float2 load, half2 store).
    // One warp-level LDG covers 4 rows x 64B contiguous -> ~4 wavefronts.
    const int c2 = tid & 7;            // channel pair 0..7
    const int rg = tid >> 3;           // row slot 0..31
    const float2* xp = (const float2*)x;
    __half2* dh = (__half2*)g_h;

    #pragma unroll 4
    for (int it = 0; it < 16; ++it) {
        const int  lr   = it * 32 + rg;        // 0..511
        const long grow = base + lr;
        const int i0 = s_idx[lr * 3], i1 = s_idx[lr * 3 + 1], i2 = s_idx[lr * 3 + 2];
        const float v0 = s_val[lr * 3], v1 = s_val[lr * 3 + 1], v2 = s_val[lr * 3 + 2];
        float2 a = xp[i0 * 8 + c2];
        float2 b = xp[i1 * 8 + c2];
        float2 c = xp[i2 * 8 + c2];
        float h0 = v0 * a.x + v1 * b.x + v2 * c.x;
        float h1 = v0 * a.y + v1 * b.y + v2 * c.y;
        dh[grow * 8 + c2] = __floats2half2_rn(h0, h1);
    }
}

// ====================== kernel 2: persistent GEMM ======================
#define MTILE    32
#define NTILES   (NVPAD / MTILE)               // 938
#define NTHREADS 512
#define GRID_K2  152

#define CHUNKS   5                             // K-chunks of 256 per tile
#define CHUNK_K  256
#define BT_BYTES     (32 * BT_STRIDE_EL * 2)   // 82432
#define OFF_A        BT_BYTES                  // 82432 (16B aligned)
#define A_ROW_B      528                       // 256 fp16 = 512 B + 16 pad
#define A_STAGE      (MTILE * A_ROW_B)         // 16896
#define NSTAGES      4
#define OFF_NEXT     (OFF_A + NSTAGES * A_STAGE)   // 150016
#define SMEM_TOTAL   (OFF_NEXT + 16)               // 150032

__device__ __forceinline__ void ldsm4(u32& r0, u32& r1, u32& r2, u32& r3, u32 addr) {
    asm volatile("ldmatrix.sync.aligned.m8n8.x4.shared.b16 {%0,%1,%2,%3}, [%4];"
        : "=r"(r0), "=r"(r1), "=r"(r2), "=r"(r3) : "r"(addr));
}
__device__ __forceinline__ void mma_f16(float* d, const u32* a, u32 b0, u32 b1) {
    asm volatile(
        "mma.sync.aligned.m16n8k16.row.col.f32.f16.f16.f32 "
        "{%0,%1,%2,%3}, {%4,%5,%6,%7}, {%8,%9}, {%0,%1,%2,%3};"
        : "+f"(d[0]), "+f"(d[1]), "+f"(d[2]), "+f"(d[3])
        : "r"(a[0]), "r"(a[1]), "r"(a[2]), "r"(a[3]), "r"(b0), "r"(b1));
}
__device__ __forceinline__ void cp16(u32 dst, const void* src) {
    asm volatile("cp.async.cg.shared.global [%0], [%1], 16;"
                 :: "r"(dst), "l"(src) : "memory");
}

// copy A chunk c (k = c*256 .. c*256+255) of tile `tl` into stage s:
// 32 rows x 512 B = 1024 16B pieces, 2 cp.async per thread
__device__ __forceinline__ void issue_copy(int tl, int c, int s, u32 sb, int tid)
{
    const int row = tid >> 4;              // 0..31
    const int q   = tid & 15;
    const __half* src = g_h + (size_t)(tl * MTILE + row) * KTOT + c * CHUNK_K;
    const u32 dst = sb + OFF_A + s * A_STAGE + row * A_ROW_B;
    cp16(dst + q * 16,        src + q * 8);
    cp16(dst + (q + 16) * 16, src + (q + 16) * 8);
}

__global__ __launch_bounds__(NTHREADS, 1)
void geo_mma_kernel()
{
    extern __shared__ char smem[];
    const u32 sb   = s2u(smem);
    const int tid  = threadIdx.x;
    const int warp = tid >> 5;             // == t value
    const int lane = tid & 31;

    // ---- load B once (group 0): full 82432 bytes ----
    {
        const char* src = (const char*)g_bt;
        for (int q = tid; q < BT_BYTES / 16; q += NTHREADS)
            cp16(sb + q * 16, src + q * 16);
        asm volatile("cp.async.commit_group;" ::: "memory");
    }

    // ldmatrix lane addressing (validated round 8)
    const u32 a_lane = (u32)(((lane & 7) + ((lane >> 3) & 1) * 8) * A_ROW_B
                             + ((lane >> 4) & 1) * 16);
    const u32 b_row  = (u32)((lane & 7) + ((lane >> 4) & 1) * 8);
    const u32 b_lane = b_row * (BT_STRIDE_EL * 2) + (u32)(((lane >> 3) & 1) * 16);
    const u32 bbase  = sb;
    int* s_next = (int*)(smem + OFF_NEXT);

    if (tid == 0) *s_next = atomicAdd(&g_ctr, 1);
    __syncthreads();
    int tile = *s_next;

    // prime pipeline: chunks 0,1,2 of first tile
    if (tile < NTILES) issue_copy(tile, 0, 0, sb, tid);
    asm volatile("cp.async.commit_group;" ::: "memory");
    if (tile < NTILES) issue_copy(tile, 1, 1, sb, tid);
    asm volatile("cp.async.commit_group;" ::: "memory");
    if (tile < NTILES) issue_copy(tile, 2, 2, sb, tid);
    asm volatile("cp.async.commit_group;" ::: "memory");

    int ist = 3;    // stage for next issued chunk
    int cst = 0;    // stage of chunk being consumed

    while (tile < NTILES) {
        const int vbase = tile * MTILE;

        float acc[2][4][4];
        #pragma unroll
        for (int m = 0; m < 2; ++m)
            #pragma unroll
            for (int n = 0; n < 4; ++n)
                #pragma unroll
                for (int q = 0; q < 4; ++q) acc[m][n][q] = 0.f;

        for (int c = 0; c < CHUNKS; ++c) {
            asm volatile("cp.async.wait_group 2;" ::: "memory");
            __syncthreads();               // chunk c visible; stage ist free

            if (c == 0 && tid == 0) *s_next = atomicAdd(&g_ctr, 1);

            // prefetch chunk c+3 (may belong to next tile; s_next readable
            // for c>=1 thanks to per-chunk syncthreads)
            {
                int pt = tile, pc = c + 3;
                if (pc >= CHUNKS) { pt = *s_next; pc -= CHUNKS; }
                if (pt < NTILES) issue_copy(pt, pc, ist, sb, tid);
                asm volatile("cp.async.commit_group;" ::: "memory");
                ist = (ist + 1 == NSTAGES) ? 0 : ist + 1;
            }

            const u32 abase = sb + OFF_A + cst * A_STAGE;
            cst = (cst + 1 == NSTAGES) ? 0 : cst + 1;
            int wbin = (16 * c + 5 * warp) % 80;

            #pragma unroll
            for (int j = 0; j < 16; ++j) {
                const u32 boff = b_lane + (u32)wbin * 32;
                u32 bh[2][4];
                ldsm4(bh[0][0], bh[0][1], bh[0][2], bh[0][3], bbase + boff);
                ldsm4(bh[1][0], bh[1][1], bh[1][2], bh[1][3],
                      bbase + boff + 16 * BT_STRIDE_EL * 2);

                #pragma unroll
                for (int mt = 0; mt < 2; ++mt) {
                    const u32 aaddr = abase + (u32)(mt * 16 * A_ROW_B + j * 32) + a_lane;
                    u32 ah[4];
                    ldsm4(ah[0], ah[1], ah[2], ah[3], aaddr);
                    #pragma unroll
                    for (int nt = 0; nt < 4; ++nt)
                        mma_f16(acc[mt][nt], ah,
                                bh[nt >> 1][(nt & 1) * 2], bh[nt >> 1][(nt & 1) * 2 + 1]);
                }
                ++wbin; if (wbin == 80) wbin = 0;
            }
        }

        // ---- epilogue: STG this warp's t-slab (no barrier needed) ----
        {
            float* basep = g_part + ((size_t)warp * NVPAD + vbase) * 32;
            #pragma unroll
            for (int mt = 0; mt < 2; ++mt)
                #pragma unroll
                for (int nt = 0; nt < 4; ++nt) {
                    int v = mt * 16 + (lane >> 2);
                    int o = nt * 8 + (lane & 3) * 2;
                    *(float2*)(basep + v * 32 + o) =
                        make_float2(acc[mt][nt][0], acc[mt][nt][1]);
                    *(float2*)(basep + (v + 8) * 32 + o) =
                        make_float2(acc[mt][nt][2], acc[mt][nt][3]);
                }
        }
        tile = *s_next;   // written at c==0, ordered by chunk syncs since
    }
}

// ====================== kernel 3: max over t ======================
__global__ __launch_bounds__(256)
void geo_max_kernel(float* __restrict__ out)
{
    const int idx = blockIdx.x * 256 + threadIdx.x;     // float4 index
    if (idx >= NVERT * 8) return;
    const float4* p = (const float4*)g_part;
    float4 m = p[idx];
    #pragma unroll
    for (int t = 1; t < 16; ++t) {
        float4 v = p[(size_t)t * NVPAD * 8 + idx];
        m.x = fmaxf(m.x, v.x);
        m.y = fmaxf(m.y, v.y);
        m.z = fmaxf(m.z, v.z);
        m.w = fmaxf(m.w, v.w);
    }
    ((float4*)out)[idx] = m;
}

extern "C" void kernel_launch(void* const* d_in, const int* in_sizes, int n_in,
                              void* d_out, int out_size)
{
    const float* x    = (const float*)d_in[0];
    const int*   cidx = (const int*)  d_in[1];
    const float* cval = (const float*)d_in[2];
    const float* wts  = (const float*)d_in[3];
    float* out = (float*)d_out;

    geo_prep_b<<<40, 512>>>(wts);
    geo_gather_kernel<<<(NROWS + RPB - 1) / RPB, K1T>>>(x, cidx, cval);

    cudaFuncSetAttribute(geo_mma_kernel,
                         cudaFuncAttributeMaxDynamicSharedMemorySize, SMEM_TOTAL);
    geo_mma_kernel<<<GRID_K2, NTHREADS, SMEM_TOTAL>>>();

    geo_max_kernel<<<(NVERT * 8 + 255) / 256, 256>>>(out);
}